// round 12
// baseline (speedup 1.0000x reference)
#include <cuda_runtime.h>
#include <cuda_bf16.h>
#include <cstdint>

typedef unsigned long long u64;

#define N_PTS 16384
#define M_CTR 4096
#define NNB   32
#define R2F   0.04f
#define NROWS (M_CTR*NNB)
#define KP    144
#define CAP   256
#define CLSZ  8               // FPS cluster size
#define PPC   (N_PTS/CLSZ)    // 2048 points per CTA
#define FPT   4               // points per thread (512 thr/CTA)
#define NSLOT 128             // 8 CTAs x 16 warps
#define KNC   16              // centers per knn CTA

// ---------------- device scratch ----------------------------------------
__device__ __align__(16) float4 g_pos4[N_PTS];
__device__ __align__(16) float4 g_center[M_CTR];
__device__ int   g_cols[NROWS];
__device__ int   g_cnt[M_CTR];
__device__ int   g_off[M_CTR];
__device__ int   g_nv;
__device__ int   g_rows[NROWS];
__device__ __align__(16) float g_W1p[KP*128];
__device__ __align__(16) float g_W2p[KP*128];
__device__ __align__(16) float g_W3p[KP*256];
__device__ __align__(16) float g_A [(size_t)NROWS*KP];
__device__ __align__(16) float g_H1[(size_t)NROWS*KP];
__device__ __align__(16) float g_H2[(size_t)NROWS*KP];
__device__ __align__(16) float g_H3[(size_t)NROWS*256];

// ---------------- f32x2 helpers -----------------------------------------
__device__ __forceinline__ u64 pk(float lo, float hi) {
    u64 r; asm("mov.b64 %0,{%1,%2};" : "=l"(r) : "f"(lo), "f"(hi)); return r;
}
__device__ __forceinline__ void upk(float& lo, float& hi, u64 v) {
    asm("mov.b64 {%0,%1},%2;" : "=f"(lo), "=f"(hi) : "l"(v));
}
__device__ __forceinline__ u64 add2(u64 a, u64 b) {
    u64 r; asm("add.rn.f32x2 %0,%1,%2;" : "=l"(r) : "l"(a), "l"(b)); return r;
}
__device__ __forceinline__ u64 mul2(u64 a, u64 b) {
    u64 r; asm("mul.rn.f32x2 %0,%1,%2;" : "=l"(r) : "l"(a), "l"(b)); return r;
}
__device__ __forceinline__ u64 fma2(u64 a, u64 b, u64 c) {
    u64 r; asm("fma.rn.f32x2 %0,%1,%2,%3;" : "=l"(r) : "l"(a), "l"(b), "l"(c)); return r;
}

// ---------------- cluster / mbarrier PTX helpers -------------------------
__device__ __forceinline__ unsigned sh_u32(const void* p) {
    return (unsigned)__cvta_generic_to_shared(p);
}
__device__ __forceinline__ unsigned mapa_sh(unsigned addr, unsigned rank) {
    unsigned r;
    asm("mapa.shared::cluster.u32 %0, %1, %2;" : "=r"(r) : "r"(addr), "r"(rank));
    return r;
}
__device__ __forceinline__ void mbar_init(unsigned a, unsigned cnt) {
    asm volatile("mbarrier.init.shared.b64 [%0], %1;" :: "r"(a), "r"(cnt) : "memory");
}
__device__ __forceinline__ void mbar_expect_tx(unsigned a, unsigned bytes) {
    asm volatile("mbarrier.arrive.expect_tx.shared::cta.b64 _, [%0], %1;"
                 :: "r"(a), "r"(bytes) : "memory");
}
__device__ __forceinline__ void st_async_u64(unsigned a, u64 v, unsigned mbar) {
    asm volatile("st.async.shared::cluster.mbarrier::complete_tx::bytes.b64 [%0], %1, [%2];"
                 :: "r"(a), "l"(v), "r"(mbar) : "memory");
}
__device__ __forceinline__ void mbar_wait_cluster(unsigned a, int phase) {
    asm volatile(
        "{\n\t"
        ".reg .pred P;\n\t"
        "W_%=:\n\t"
        "mbarrier.try_wait.parity.acquire.cluster.shared::cta.b64 P, [%0], %1, 0x989680;\n\t"
        "@P bra.uni D_%=;\n\t"
        "bra.uni W_%=;\n\t"
        "D_%=:\n\t"
        "}" :: "r"(a), "r"(phase) : "memory");
}
__device__ __forceinline__ void cluster_sync_all() {
    asm volatile("barrier.cluster.arrive.aligned;" ::: "memory");
    asm volatile("barrier.cluster.wait.aligned;" ::: "memory");
}
__device__ __forceinline__ unsigned redux_max_u32(unsigned v) {
    unsigned r;
    asm("redux.sync.max.u32 %0, %1, 0xffffffff;" : "=r"(r) : "r"(v));
    return r;
}

// ---------------- prep ----------------------------------------------------
__global__ void __launch_bounds__(256) prep_kernel(
    const float* __restrict__ x,
    const float* __restrict__ W1, const float* __restrict__ b1,
    const float* __restrict__ W2, const float* __restrict__ b2,
    const float* __restrict__ W3, const float* __restrict__ b3)
{
    int i = blockIdx.x * 256 + threadIdx.x;
    if (i < N_PTS) {
        const float* row = x + (size_t)i * 131;
        g_pos4[i] = make_float4(row[0], row[1], row[2], 0.f);
    }
    if (i < KP * 128) {
        int k = i >> 7, j = i & 127;
        g_W1p[i] = (k < 131) ? W1[k * 128 + j] : (k == 131 ? b1[j] : 0.f);
        g_W2p[i] = (k < 128) ? W2[k * 128 + j] : (k == 128 ? b2[j] : 0.f);
    }
    if (i < KP * 256) {
        int k = i >> 8, j = i & 255;
        g_W3p[i] = (k < 128) ? W3[k * 256 + j] : (k == 128 ? b3[j] : 0.f);
    }
}

// ---------------- FPS: 8 CTAs x 512 thr, key-only all-to-all ---------------
// 4 pts/thread halves the serial dist+select segment; 128 warp-best slots.
#define FPS_SMEM_BYTES (3 * N_PTS * 4)    // s_px/s_py/s_pz = 192KB

__global__ void __launch_bounds__(512, 1) __cluster_dims__(CLSZ, 1, 1)
fps_kernel() {
    extern __shared__ float s_dyn[];
    float* s_px = s_dyn;
    float* s_py = s_dyn + N_PTS;
    float* s_pz = s_dyn + 2 * N_PTS;
    __shared__ __align__(16) u64 s_mbk[2][NSLOT];   // 128 warp-best keys
    __shared__ __align__(8)  u64 s_bar[2];

    int tid = threadIdx.x, lane = tid & 31, warp = tid >> 5;
    unsigned rank;
    asm("mov.u32 %0, %%cluster_ctarank;" : "=r"(rank));
    int pbase = (int)rank * PPC + tid;
    int slotid = (int)rank * 16 + warp;             // my warp's mailbox slot

    // full position replica in smem (one-time)
    for (int i = tid; i < N_PTS; i += 512) {
        float4 p = g_pos4[i];
        s_px[i] = p.x; s_py[i] = p.y; s_pz[i] = p.z;
    }
    // own-shard coords register-resident; min_d as u32 bits
    u64 PX[2], PY[2], PZ[2];
    unsigned mb[FPT];
    unsigned nlo[FPT];                              // ~oidx, loop-invariant
#pragma unroll
    for (int q = 0; q < 2; q++) {
        float4 a = g_pos4[pbase + (2 * q) * 512];
        float4 b = g_pos4[pbase + (2 * q + 1) * 512];
        PX[q] = pk(a.x, b.x); PY[q] = pk(a.y, b.y); PZ[q] = pk(a.z, b.z);
        mb[2 * q] = 0x7f800000u;
        mb[2 * q + 1] = 0x7f800000u;
    }
#pragma unroll
    for (int i = 0; i < FPT; i++) nlo[i] = ~(unsigned)(pbase + i * 512);

    if (tid == 0) {
        mbar_init(sh_u32(&s_bar[0]), 1);   // 1 arrive (expect_tx) + 128*8 tx bytes
        mbar_init(sh_u32(&s_bar[1]), 1);
    }
    // hoisted remote addresses for sending lanes (dst = lane&7)
    unsigned dst = (unsigned)(lane & 7);
    unsigned rab0 = mapa_sh(sh_u32(&s_bar[0]), dst);
    unsigned rab1 = mapa_sh(sh_u32(&s_bar[1]), dst);
    unsigned rak0 = mapa_sh(sh_u32(&s_mbk[0][slotid]), dst);
    unsigned rak1 = mapa_sh(sh_u32(&s_mbk[1][slotid]), dst);

    __syncthreads();
    cluster_sync_all();     // barriers + replica visible before any st.async

    float4 c0 = g_pos4[0];
    float cx = c0.x, cy = c0.y, cz = c0.z;
    if (rank == 0 && tid == 0) g_center[0] = make_float4(cx, cy, cz, 0.f);

    int par0 = 0, par1 = 0;

    for (int k = 1; k < M_CTR; k++) {
        int buf = k & 1;
        // post this phase's expected bytes early (128 senders x 8B)
        if (tid == 0) mbar_expect_tx(sh_u32(&s_bar[buf]), NSLOT * 8);

        // --- packed exact distance update (rn ops, (x2+y2)+z2, p+(-c)) ---
        u64 ncx = pk(-cx, -cx), ncy = pk(-cy, -cy), ncz = pk(-cz, -cz);
#pragma unroll
        for (int q = 0; q < 2; q++) {
            u64 dx = add2(PX[q], ncx);
            u64 dy = add2(PY[q], ncy);
            u64 dz = add2(PZ[q], ncz);
            u64 s  = add2(add2(mul2(dx, dx), mul2(dy, dy)), mul2(dz, dz));
            float d0, d1; upk(d0, d1, s);
            mb[2 * q]     = min(mb[2 * q],     __float_as_uint(d0));
            mb[2 * q + 1] = min(mb[2 * q + 1], __float_as_uint(d1));
        }
        // --- per-thread select: direct u64 key max (tie -> min oidx) ------
        u64 key = ((u64)mb[0] << 32) | nlo[0];
#pragma unroll
        for (int i = 1; i < FPT; i++) {
            u64 ki = ((u64)mb[i] << 32) | nlo[i];
            if (ki > key) key = ki;
        }
        // --- warp argmax via redux (keys only) ----------------------------
        u64 kbest;
        {
            unsigned vb = (unsigned)(key >> 32);
            unsigned mx = redux_max_u32(vb);
            unsigned cand = (vb == mx) ? (unsigned)key : 0u;
            unsigned lw = redux_max_u32(cand);
            kbest = ((u64)mx << 32) | lw;
        }
        // --- lanes 0..7 send warp-best key to slot rank*16+warp of all CTAs
        if (lane < CLSZ)
            st_async_u64(buf ? rak1 : rak0, kbest, buf ? rab1 : rab0);

        // --- wait for all 1024 bytes, pick global winner (per-warp) -------
        mbar_wait_cluster(sh_u32(&s_bar[buf]), buf ? par1 : par0);
        if (buf) par1 ^= 1; else par0 ^= 1;

        {
            u64 k1 = s_mbk[buf][lane];
            u64 k2 = s_mbk[buf][lane + 32];
            u64 k3 = s_mbk[buf][lane + 64];
            u64 k4 = s_mbk[buf][lane + 96];
            u64 kk = (k2 > k1) ? k2 : k1;
            if (k3 > kk) kk = k3;
            if (k4 > kk) kk = k4;
            unsigned vb = (unsigned)(kk >> 32);
            unsigned mx = redux_max_u32(vb);
            unsigned cand = (vb == mx) ? (unsigned)kk : 0u;
            unsigned lw = redux_max_u32(cand);
            int oidx = (int)(~lw);                   // winner point index
            cx = s_px[oidx]; cy = s_py[oidx]; cz = s_pz[oidx];  // broadcast LDS
        }
        if (rank == 0 && tid == 0) g_center[k] = make_float4(cx, cy, cz, 0.f);
    }
    cluster_sync_all();
}

// ---------------- radius-KNN: 16 centers per CTA share tiles ---------------
#define KNN_SMEM_BYTES (65536 + KNC * CAP * 8)      // tiles 64KB + lists 32KB

__global__ void __launch_bounds__(512) knn_kernel() {
    extern __shared__ char sm_raw[];
    float4* s_t   = (float4*)sm_raw;                 // 4096 float4 = 64KB
    u64*    s_lst = (u64*)(sm_raw + 65536);          // KNC x CAP keys
    int tid = threadIdx.x, lane = tid & 31, warp = tid >> 5;
    int c = blockIdx.x * KNC + warp;
    u64* lst = s_lst + warp * CAP;
    float4 ct = g_center[c];

    int cnt = 0;
    for (int tile = 0; tile < 4; tile++) {
        __syncthreads();
        for (int i = tid; i < 4096; i += 512) s_t[i] = g_pos4[tile * 4096 + i];
        __syncthreads();
        for (int i = lane; i < 4096; i += 32) {
            float4 p = s_t[i];
            float dx = __fsub_rn(ct.x, p.x);
            float dy = __fsub_rn(ct.y, p.y);
            float dz = __fsub_rn(ct.z, p.z);
            float d2 = __fadd_rn(__fadd_rn(__fmul_rn(dx, dx), __fmul_rn(dy, dy)),
                                 __fmul_rn(dz, dz));
            bool ok = d2 <= R2F;
            unsigned mk = __ballot_sync(0xffffffffu, ok);
            if (ok) {
                int pos = cnt + __popc(mk & ((1u << lane) - 1u));
                if (pos < CAP)
                    lst[pos] = ((u64)__float_as_uint(d2) << 32)
                               | (unsigned)(tile * 4096 + i);
            }
            cnt += __popc(mk);
        }
    }
    if (cnt > CAP) cnt = CAP;
    __syncwarp();

    if (cnt <= NNB) {
        int v = (lane < cnt) ? (int)(unsigned)(lst[lane] & 0xffffffffu) : -1;
        g_cols[c * NNB + lane] = v;
        if (lane == 0) g_cnt[c] = cnt;
    } else {
        for (int i = lane; i < cnt; i += 32) {
            u64 ki = lst[i];
            int rnk = 0;
            for (int j = 0; j < cnt; j++) rnk += (lst[j] < ki);
            if (rnk < NNB)
                g_cols[c * NNB + rnk] = (int)(unsigned)(ki & 0xffffffffu);
        }
        if (lane == 0) g_cnt[c] = NNB;
    }
}

// ---------------- exclusive scan of g_cnt (ENV CANARY — DO NOT TOUCH) ------
__global__ void __launch_bounds__(512, 1) scan_kernel() {
    __shared__ int s_ws[16];
    int tid = threadIdx.x, lane = tid & 31, warp = tid >> 5;
    int v[8], run = 0;
#pragma unroll
    for (int i = 0; i < 8; i++) { v[i] = g_cnt[tid * 8 + i]; run += v[i]; }
    int tot = run;
    int pre = tot;
#pragma unroll
    for (int o = 1; o < 32; o <<= 1) {
        int t = __shfl_up_sync(0xffffffffu, pre, o);
        if (lane >= o) pre += t;
    }
    if (lane == 31) s_ws[warp] = pre;
    int excl = pre - tot;
    __syncthreads();
    if (warp == 0) {
        int w = (lane < 16) ? s_ws[lane] : 0;
#pragma unroll
        for (int o = 1; o < 16; o <<= 1) {
            int t = __shfl_up_sync(0xffffffffu, w, o);
            if (lane >= o) w += t;
        }
        if (lane < 16) s_ws[lane] = w;
    }
    __syncthreads();
    int base = (warp > 0) ? s_ws[warp - 1] : 0;
    int off = base + excl;
#pragma unroll
    for (int i = 0; i < 8; i++) { g_off[tid * 8 + i] = off; off += v[i]; }
    if (tid == 511) g_nv = off;
}

// ---------------- row map: compacted row -> (center,slot) ------------------
__global__ void __launch_bounds__(256) rowmap_kernel() {
    int idx = blockIdx.x * 256 + threadIdx.x;
    int c = idx >> 5, s = idx & 31;
    if (s < g_cnt[c]) g_rows[g_off[c] + s] = idx;
}

// ---------------- gather + bias-pad (compacted rows only) ------------------
__global__ void __launch_bounds__(256) gather_kernel(const float* __restrict__ x) {
    int lane = threadIdx.x & 31;
    int warp = threadIdx.x >> 5;
    int nv = g_nv;
    float4 one0 = make_float4(1.f, 0.f, 0.f, 0.f);
    float4 z    = make_float4(0.f, 0.f, 0.f, 0.f);
    for (int r = blockIdx.x * 8 + warp; r < nv; r += 512 * 8) {
        int rid = g_rows[r];
        int c   = rid >> 5;
        int col = g_cols[rid];
        float* a = g_A + (size_t)r * KP;
        const float* xr = x + (size_t)col * 131 + 3 + 4 * lane;
        ((float4*)a)[lane] = make_float4(xr[0], xr[1], xr[2], xr[3]);
        if (lane < 4) {                      // A pad cols 128..143
            float4 e = z;
            if (lane == 0) {
                float4 p = g_pos4[col]; float4 ct = g_center[c];
                e = make_float4(p.x - ct.x, p.y - ct.y, p.z - ct.z, 1.0f);
            }
            ((float4*)a)[32 + lane] = e;
        } else if (lane < 8) {               // H1 bias cols
            ((float4*)(g_H1 + (size_t)r * KP + 128))[lane - 4] =
                (lane == 4) ? one0 : z;
        } else if (lane < 12) {              // H2 bias cols
            ((float4*)(g_H2 + (size_t)r * KP + 128))[lane - 8] =
                (lane == 8) ? one0 : z;
        }
    }
}

// ---------------- tiled fp32 GEMM + relu (early-exit past NV) --------------
template<int L>
__global__ void __launch_bounds__(256) sgemm_kernel() {
    size_t bRow = (size_t)blockIdx.x * 128;
    if ((int)bRow >= g_nv) return;
    const float* A = (L == 0) ? g_A  : (L == 1) ? g_H1 : g_H2;
    const float* B = (L == 0) ? g_W1p : (L == 1) ? g_W2p : g_W3p;
    float*       C = (L == 0) ? g_H1 : (L == 1) ? g_H2 : g_H3;
    const int ldb = (L == 2) ? 256 : 128;
    const int ldc = (L == 2) ? 256 : KP;

    __shared__ __align__(16) float As[16][132];
    __shared__ __align__(16) float Bs[16][132];
    int t  = threadIdx.x;
    int tx = t & 15, ty = t >> 4;
    int    bCol = blockIdx.y * 128;

    u64 acc[8][4];
#pragma unroll
    for (int i = 0; i < 8; i++)
#pragma unroll
        for (int p = 0; p < 4; p++) acc[i][p] = 0ull;

    for (int k0 = 0; k0 < KP; k0 += 16) {
#pragma unroll
        for (int e2 = 0; e2 < 2; e2++) {
            int e = t * 2 + e2;
            int r = e >> 2, c4 = e & 3;
            float4 f = *(const float4*)(A + (bRow + r) * KP + k0 + c4 * 4);
            As[c4 * 4 + 0][r] = f.x; As[c4 * 4 + 1][r] = f.y;
            As[c4 * 4 + 2][r] = f.z; As[c4 * 4 + 3][r] = f.w;
        }
#pragma unroll
        for (int e2 = 0; e2 < 2; e2++) {
            int e = t * 2 + e2;
            int r = e >> 5, c4 = e & 31;
            *(float4*)&Bs[r][c4 * 4] =
                *(const float4*)(B + (size_t)(k0 + r) * ldb + bCol + c4 * 4);
        }
        __syncthreads();
#pragma unroll
        for (int kk = 0; kk < 16; kk++) {
            longlong2 bb0 = *(const longlong2*)&Bs[kk][tx * 8];
            longlong2 bb1 = *(const longlong2*)&Bs[kk][tx * 8 + 4];
            u64 b[4] = { (u64)bb0.x, (u64)bb0.y, (u64)bb1.x, (u64)bb1.y };
            float4 a03 = *(const float4*)&As[kk][ty * 8];
            float4 a47 = *(const float4*)&As[kk][ty * 8 + 4];
            float a[8] = { a03.x, a03.y, a03.z, a03.w, a47.x, a47.y, a47.z, a47.w };
#pragma unroll
            for (int i = 0; i < 8; i++) {
                u64 aa = pk(a[i], a[i]);
#pragma unroll
                for (int p = 0; p < 4; p++) acc[i][p] = fma2(aa, b[p], acc[i][p]);
            }
        }
        __syncthreads();
    }
#pragma unroll
    for (int i = 0; i < 8; i++) {
        float* cr = C + (bRow + ty * 8 + i) * (size_t)ldc + bCol + tx * 8;
#pragma unroll
        for (int p = 0; p < 4; p++) {
            float lo, hi; upk(lo, hi, acc[i][p]);
            ((float2*)cr)[p] = make_float2(fmaxf(lo, 0.f), fmaxf(hi, 0.f));
        }
    }
}

// ---------------- masked max-pool over compacted rows ----------------------
__global__ void __launch_bounds__(256) pool_kernel(float* __restrict__ out) {
    int c = blockIdx.x, j = threadIdx.x;
    int off = g_off[c], cnt = g_cnt[c];
    float acc = 0.0f;
    if (cnt > 0) {
        acc = g_H3[(size_t)off * 256 + j];
        for (int s = 1; s < cnt; s++)
            acc = fmaxf(acc, g_H3[(size_t)(off + s) * 256 + j]);
    }
    out[(size_t)c * 256 + j] = acc;
}

// ---------------- launcher ----------------------------------------------
extern "C" void kernel_launch(void* const* d_in, const int* in_sizes, int n_in,
                              void* d_out, int out_size) {
    const float* x  = (const float*)d_in[0];
    const float* W1 = (const float*)d_in[1];
    const float* b1 = (const float*)d_in[2];
    const float* W2 = (const float*)d_in[3];
    const float* b2 = (const float*)d_in[4];
    const float* W3 = (const float*)d_in[5];
    const float* b3 = (const float*)d_in[6];
    float* out = (float*)d_out;

    cudaFuncSetAttribute(fps_kernel, cudaFuncAttributeMaxDynamicSharedMemorySize,
                         FPS_SMEM_BYTES);
    cudaFuncSetAttribute(knn_kernel, cudaFuncAttributeMaxDynamicSharedMemorySize,
                         KNN_SMEM_BYTES);

    prep_kernel<<<144, 256>>>(x, W1, b1, W2, b2, W3, b3);
    fps_kernel<<<CLSZ, 512, FPS_SMEM_BYTES>>>();
    knn_kernel<<<M_CTR / KNC, 512, KNN_SMEM_BYTES>>>();
    scan_kernel<<<1, 512>>>();
    rowmap_kernel<<<NROWS / 256, 256>>>();
    gather_kernel<<<512, 256>>>(x);
    sgemm_kernel<0><<<dim3(NROWS / 128, 1), 256>>>();
    sgemm_kernel<1><<<dim3(NROWS / 128, 1), 256>>>();
    sgemm_kernel<2><<<dim3(NROWS / 128, 2), 256>>>();
    pool_kernel<<<M_CTR, 256>>>(out);
}

// round 13
// speedup vs baseline: 1.1699x; 1.1699x over previous
#include <cuda_runtime.h>
#include <cuda_bf16.h>
#include <cstdint>

typedef unsigned long long u64;

#define N_PTS 16384
#define M_CTR 4096
#define NNB   32
#define R2F   0.04f
#define NROWS (M_CTR*NNB)
#define KP    144
#define CAP   256
#define CLSZ  8               // FPS cluster size
#define PPC   (N_PTS/CLSZ)    // 2048 points per CTA
#define FPT   8               // points per thread (256 thr/CTA)
#define NSLOT 64              // 8 CTAs x 8 warps
#define KNC   16              // centers per knn CTA

// ---------------- device scratch ----------------------------------------
__device__ __align__(16) float4 g_pos4[N_PTS];
__device__ __align__(16) float4 g_center[M_CTR];
__device__ int   g_cols[NROWS];
__device__ int   g_cnt[M_CTR];
__device__ int   g_off[M_CTR];
__device__ int   g_nv;
__device__ int   g_rows[NROWS];
__device__ __align__(16) float g_W1p[KP*128];
__device__ __align__(16) float g_W2p[KP*128];
__device__ __align__(16) float g_W3p[KP*256];
__device__ __align__(16) float g_A [(size_t)NROWS*KP];
__device__ __align__(16) float g_H1[(size_t)NROWS*KP];
__device__ __align__(16) float g_H2[(size_t)NROWS*KP];
__device__ __align__(16) float g_H3[(size_t)NROWS*256];

// ---------------- f32x2 helpers -----------------------------------------
__device__ __forceinline__ u64 pk(float lo, float hi) {
    u64 r; asm("mov.b64 %0,{%1,%2};" : "=l"(r) : "f"(lo), "f"(hi)); return r;
}
__device__ __forceinline__ void upk(float& lo, float& hi, u64 v) {
    asm("mov.b64 {%0,%1},%2;" : "=f"(lo), "=f"(hi) : "l"(v));
}
__device__ __forceinline__ u64 add2(u64 a, u64 b) {
    u64 r; asm("add.rn.f32x2 %0,%1,%2;" : "=l"(r) : "l"(a), "l"(b)); return r;
}
__device__ __forceinline__ u64 mul2(u64 a, u64 b) {
    u64 r; asm("mul.rn.f32x2 %0,%1,%2;" : "=l"(r) : "l"(a), "l"(b)); return r;
}
__device__ __forceinline__ u64 fma2(u64 a, u64 b, u64 c) {
    u64 r; asm("fma.rn.f32x2 %0,%1,%2,%3;" : "=l"(r) : "l"(a), "l"(b), "l"(c)); return r;
}

// ---------------- cluster / mbarrier PTX helpers -------------------------
__device__ __forceinline__ unsigned sh_u32(const void* p) {
    return (unsigned)__cvta_generic_to_shared(p);
}
__device__ __forceinline__ unsigned mapa_sh(unsigned addr, unsigned rank) {
    unsigned r;
    asm("mapa.shared::cluster.u32 %0, %1, %2;" : "=r"(r) : "r"(addr), "r"(rank));
    return r;
}
__device__ __forceinline__ void mbar_init(unsigned a, unsigned cnt) {
    asm volatile("mbarrier.init.shared.b64 [%0], %1;" :: "r"(a), "r"(cnt) : "memory");
}
__device__ __forceinline__ void mbar_expect_tx(unsigned a, unsigned bytes) {
    asm volatile("mbarrier.arrive.expect_tx.shared::cta.b64 _, [%0], %1;"
                 :: "r"(a), "r"(bytes) : "memory");
}
__device__ __forceinline__ void st_async_u64(unsigned a, u64 v, unsigned mbar) {
    asm volatile("st.async.shared::cluster.mbarrier::complete_tx::bytes.b64 [%0], %1, [%2];"
                 :: "r"(a), "l"(v), "r"(mbar) : "memory");
}
__device__ __forceinline__ void mbar_wait_cluster(unsigned a, int phase) {
    asm volatile(
        "{\n\t"
        ".reg .pred P;\n\t"
        "W_%=:\n\t"
        "mbarrier.try_wait.parity.acquire.cluster.shared::cta.b64 P, [%0], %1, 0x989680;\n\t"
        "@P bra.uni D_%=;\n\t"
        "bra.uni W_%=;\n\t"
        "D_%=:\n\t"
        "}" :: "r"(a), "r"(phase) : "memory");
}
__device__ __forceinline__ void cluster_sync_all() {
    asm volatile("barrier.cluster.arrive.aligned;" ::: "memory");
    asm volatile("barrier.cluster.wait.aligned;" ::: "memory");
}
__device__ __forceinline__ unsigned redux_max_u32(unsigned v) {
    unsigned r;
    asm("redux.sync.max.u32 %0, %1, 0xffffffff;" : "=r"(r) : "r"(v));
    return r;
}

// ---------------- prep ----------------------------------------------------
__global__ void __launch_bounds__(256) prep_kernel(
    const float* __restrict__ x,
    const float* __restrict__ W1, const float* __restrict__ b1,
    const float* __restrict__ W2, const float* __restrict__ b2,
    const float* __restrict__ W3, const float* __restrict__ b3)
{
    int i = blockIdx.x * 256 + threadIdx.x;
    if (i < N_PTS) {
        const float* row = x + (size_t)i * 131;
        g_pos4[i] = make_float4(row[0], row[1], row[2], 0.f);
    }
    if (i < KP * 128) {
        int k = i >> 7, j = i & 127;
        g_W1p[i] = (k < 131) ? W1[k * 128 + j] : (k == 131 ? b1[j] : 0.f);
        g_W2p[i] = (k < 128) ? W2[k * 128 + j] : (k == 128 ? b2[j] : 0.f);
    }
    if (i < KP * 256) {
        int k = i >> 8, j = i & 255;
        g_W3p[i] = (k < 128) ? W3[k * 256 + j] : (k == 128 ? b3[j] : 0.f);
    }
}

// ---------------- FPS: 8 CTAs x 256 thr (R10-identical, proven 1739) -------
#define FPS_SMEM_BYTES (3 * N_PTS * 4)    // s_px/s_py/s_pz = 192KB

__global__ void __launch_bounds__(256, 1) __cluster_dims__(CLSZ, 1, 1)
fps_kernel() {
    extern __shared__ float s_dyn[];
    float* s_px = s_dyn;
    float* s_py = s_dyn + N_PTS;
    float* s_pz = s_dyn + 2 * N_PTS;
    __shared__ __align__(16) u64 s_mbk[2][NSLOT];   // 64 warp-best keys
    __shared__ __align__(8)  u64 s_bar[2];

    int tid = threadIdx.x, lane = tid & 31, warp = tid >> 5;
    unsigned rank;
    asm("mov.u32 %0, %%cluster_ctarank;" : "=r"(rank));
    int pbase = (int)rank * PPC + tid;
    int slotid = (int)rank * 8 + warp;              // my warp's mailbox slot

    // full position replica in smem (one-time)
    for (int i = tid; i < N_PTS; i += 256) {
        float4 p = g_pos4[i];
        s_px[i] = p.x; s_py[i] = p.y; s_pz[i] = p.z;
    }
    // own-shard coords register-resident; min_d as u32 bits
    u64 PX[4], PY[4], PZ[4];
    unsigned mb[FPT];
    unsigned nlo[FPT];                              // ~oidx, loop-invariant
#pragma unroll
    for (int q = 0; q < 4; q++) {
        float4 a = g_pos4[pbase + (2 * q) * 256];
        float4 b = g_pos4[pbase + (2 * q + 1) * 256];
        PX[q] = pk(a.x, b.x); PY[q] = pk(a.y, b.y); PZ[q] = pk(a.z, b.z);
        mb[2 * q] = 0x7f800000u;
        mb[2 * q + 1] = 0x7f800000u;
    }
#pragma unroll
    for (int i = 0; i < FPT; i++) nlo[i] = ~(unsigned)(pbase + i * 256);

    if (tid == 0) {
        mbar_init(sh_u32(&s_bar[0]), 1);   // 1 arrive (expect_tx) + 64*8 tx bytes
        mbar_init(sh_u32(&s_bar[1]), 1);
    }
    // hoisted remote addresses for sending lanes (dst = lane&7)
    unsigned dst = (unsigned)(lane & 7);
    unsigned rab0 = mapa_sh(sh_u32(&s_bar[0]), dst);
    unsigned rab1 = mapa_sh(sh_u32(&s_bar[1]), dst);
    unsigned rak0 = mapa_sh(sh_u32(&s_mbk[0][slotid]), dst);
    unsigned rak1 = mapa_sh(sh_u32(&s_mbk[1][slotid]), dst);

    __syncthreads();
    cluster_sync_all();     // barriers + replica visible before any st.async

    float4 c0 = g_pos4[0];
    float cx = c0.x, cy = c0.y, cz = c0.z;
    if (rank == 0 && tid == 0) g_center[0] = make_float4(cx, cy, cz, 0.f);

    int par0 = 0, par1 = 0;

    for (int k = 1; k < M_CTR; k++) {
        int buf = k & 1;
        // post this phase's expected bytes early (64 senders x 8B)
        if (tid == 0) mbar_expect_tx(sh_u32(&s_bar[buf]), NSLOT * 8);

        // --- packed exact distance update (rn ops, (x2+y2)+z2, p+(-c)) ---
        // min on ALU pipe (u32 bits, valid: d2>=0, never -0)
        u64 ncx = pk(-cx, -cx), ncy = pk(-cy, -cy), ncz = pk(-cz, -cz);
#pragma unroll
        for (int q = 0; q < 4; q++) {
            u64 dx = add2(PX[q], ncx);
            u64 dy = add2(PY[q], ncy);
            u64 dz = add2(PZ[q], ncz);
            u64 s  = add2(add2(mul2(dx, dx), mul2(dy, dy)), mul2(dz, dz));
            float d0, d1; upk(d0, d1, s);
            mb[2 * q]     = min(mb[2 * q],     __float_as_uint(d0));
            mb[2 * q + 1] = min(mb[2 * q + 1], __float_as_uint(d1));
        }
        // --- per-thread select: direct u64 key max (tie -> min oidx) ------
        u64 key = ((u64)mb[0] << 32) | nlo[0];
#pragma unroll
        for (int i = 1; i < FPT; i++) {
            u64 ki = ((u64)mb[i] << 32) | nlo[i];
            if (ki > key) key = ki;
        }
        // --- warp argmax via redux (keys only) ----------------------------
        u64 kbest;
        {
            unsigned vb = (unsigned)(key >> 32);
            unsigned mx = redux_max_u32(vb);
            unsigned cand = (vb == mx) ? (unsigned)key : 0u;
            unsigned lw = redux_max_u32(cand);
            kbest = ((u64)mx << 32) | lw;
        }
        // --- lanes 0..7 send warp-best key to slot rank*8+warp of all CTAs -
        if (lane < CLSZ)
            st_async_u64(buf ? rak1 : rak0, kbest, buf ? rab1 : rab0);

        // --- wait for all 512 bytes, pick global winner (per-warp) --------
        mbar_wait_cluster(sh_u32(&s_bar[buf]), buf ? par1 : par0);
        if (buf) par1 ^= 1; else par0 ^= 1;

        {
            u64 k1 = s_mbk[buf][lane];
            u64 k2 = s_mbk[buf][lane + 32];
            u64 kk = (k2 > k1) ? k2 : k1;
            unsigned vb = (unsigned)(kk >> 32);
            unsigned mx = redux_max_u32(vb);
            unsigned cand = (vb == mx) ? (unsigned)kk : 0u;
            unsigned lw = redux_max_u32(cand);
            int oidx = (int)(~lw);                   // winner point index
            cx = s_px[oidx]; cy = s_py[oidx]; cz = s_pz[oidx];  // broadcast LDS
        }
        if (rank == 0 && tid == 0) g_center[k] = make_float4(cx, cy, cz, 0.f);
    }
    cluster_sync_all();
}

// ---------------- radius-KNN: 16 centers per CTA share tiles ---------------
#define KNN_SMEM_BYTES (65536 + KNC * CAP * 8)      // tiles 64KB + lists 32KB

__global__ void __launch_bounds__(512) knn_kernel() {
    extern __shared__ char sm_raw[];
    float4* s_t   = (float4*)sm_raw;                 // 4096 float4 = 64KB
    u64*    s_lst = (u64*)(sm_raw + 65536);          // KNC x CAP keys
    int tid = threadIdx.x, lane = tid & 31, warp = tid >> 5;
    int c = blockIdx.x * KNC + warp;
    u64* lst = s_lst + warp * CAP;
    float4 ct = g_center[c];

    int cnt = 0;
    for (int tile = 0; tile < 4; tile++) {
        __syncthreads();
        for (int i = tid; i < 4096; i += 512) s_t[i] = g_pos4[tile * 4096 + i];
        __syncthreads();
        for (int i = lane; i < 4096; i += 32) {
            float4 p = s_t[i];
            float dx = __fsub_rn(ct.x, p.x);
            float dy = __fsub_rn(ct.y, p.y);
            float dz = __fsub_rn(ct.z, p.z);
            float d2 = __fadd_rn(__fadd_rn(__fmul_rn(dx, dx), __fmul_rn(dy, dy)),
                                 __fmul_rn(dz, dz));
            bool ok = d2 <= R2F;
            unsigned mk = __ballot_sync(0xffffffffu, ok);
            if (ok) {
                int pos = cnt + __popc(mk & ((1u << lane) - 1u));
                if (pos < CAP)
                    lst[pos] = ((u64)__float_as_uint(d2) << 32)
                               | (unsigned)(tile * 4096 + i);
            }
            cnt += __popc(mk);
        }
    }
    if (cnt > CAP) cnt = CAP;
    __syncwarp();

    if (cnt <= NNB) {
        int v = (lane < cnt) ? (int)(unsigned)(lst[lane] & 0xffffffffu) : -1;
        g_cols[c * NNB + lane] = v;
        if (lane == 0) g_cnt[c] = cnt;
    } else {
        for (int i = lane; i < cnt; i += 32) {
            u64 ki = lst[i];
            int rnk = 0;
            for (int j = 0; j < cnt; j++) rnk += (lst[j] < ki);
            if (rnk < NNB)
                g_cols[c * NNB + rnk] = (int)(unsigned)(ki & 0xffffffffu);
        }
        if (lane == 0) g_cnt[c] = NNB;
    }
}

// ---------------- exclusive scan of g_cnt (ENV CANARY — DO NOT TOUCH) ------
__global__ void __launch_bounds__(512, 1) scan_kernel() {
    __shared__ int s_ws[16];
    int tid = threadIdx.x, lane = tid & 31, warp = tid >> 5;
    int v[8], run = 0;
#pragma unroll
    for (int i = 0; i < 8; i++) { v[i] = g_cnt[tid * 8 + i]; run += v[i]; }
    int tot = run;
    int pre = tot;
#pragma unroll
    for (int o = 1; o < 32; o <<= 1) {
        int t = __shfl_up_sync(0xffffffffu, pre, o);
        if (lane >= o) pre += t;
    }
    if (lane == 31) s_ws[warp] = pre;
    int excl = pre - tot;
    __syncthreads();
    if (warp == 0) {
        int w = (lane < 16) ? s_ws[lane] : 0;
#pragma unroll
        for (int o = 1; o < 16; o <<= 1) {
            int t = __shfl_up_sync(0xffffffffu, w, o);
            if (lane >= o) w += t;
        }
        if (lane < 16) s_ws[lane] = w;
    }
    __syncthreads();
    int base = (warp > 0) ? s_ws[warp - 1] : 0;
    int off = base + excl;
#pragma unroll
    for (int i = 0; i < 8; i++) { g_off[tid * 8 + i] = off; off += v[i]; }
    if (tid == 511) g_nv = off;
}

// ---------------- row map: compacted row -> (center,slot) ------------------
__global__ void __launch_bounds__(256) rowmap_kernel() {
    int idx = blockIdx.x * 256 + threadIdx.x;
    int c = idx >> 5, s = idx & 31;
    if (s < g_cnt[c]) g_rows[g_off[c] + s] = idx;
}

// ---------------- gather + bias-pad (compacted rows only) ------------------
__global__ void __launch_bounds__(256) gather_kernel(const float* __restrict__ x) {
    int lane = threadIdx.x & 31;
    int warp = threadIdx.x >> 5;
    int nv = g_nv;
    float4 one0 = make_float4(1.f, 0.f, 0.f, 0.f);
    float4 z    = make_float4(0.f, 0.f, 0.f, 0.f);
    for (int r = blockIdx.x * 8 + warp; r < nv; r += 512 * 8) {
        int rid = g_rows[r];
        int c   = rid >> 5;
        int col = g_cols[rid];
        float* a = g_A + (size_t)r * KP;
        const float* xr = x + (size_t)col * 131 + 3 + 4 * lane;
        ((float4*)a)[lane] = make_float4(xr[0], xr[1], xr[2], xr[3]);
        if (lane < 4) {                      // A pad cols 128..143
            float4 e = z;
            if (lane == 0) {
                float4 p = g_pos4[col]; float4 ct = g_center[c];
                e = make_float4(p.x - ct.x, p.y - ct.y, p.z - ct.z, 1.0f);
            }
            ((float4*)a)[32 + lane] = e;
        } else if (lane < 8) {               // H1 bias cols
            ((float4*)(g_H1 + (size_t)r * KP + 128))[lane - 4] =
                (lane == 4) ? one0 : z;
        } else if (lane < 12) {              // H2 bias cols
            ((float4*)(g_H2 + (size_t)r * KP + 128))[lane - 8] =
                (lane == 8) ? one0 : z;
        }
    }
}

// ---------------- tiled fp32 GEMM + relu (early-exit past NV) --------------
template<int L>
__global__ void __launch_bounds__(256) sgemm_kernel() {
    size_t bRow = (size_t)blockIdx.x * 128;
    if ((int)bRow >= g_nv) return;
    const float* A = (L == 0) ? g_A  : (L == 1) ? g_H1 : g_H2;
    const float* B = (L == 0) ? g_W1p : (L == 1) ? g_W2p : g_W3p;
    float*       C = (L == 0) ? g_H1 : (L == 1) ? g_H2 : g_H3;
    const int ldb = (L == 2) ? 256 : 128;
    const int ldc = (L == 2) ? 256 : KP;

    __shared__ __align__(16) float As[16][132];
    __shared__ __align__(16) float Bs[16][132];
    int t  = threadIdx.x;
    int tx = t & 15, ty = t >> 4;
    int    bCol = blockIdx.y * 128;

    u64 acc[8][4];
#pragma unroll
    for (int i = 0; i < 8; i++)
#pragma unroll
        for (int p = 0; p < 4; p++) acc[i][p] = 0ull;

    for (int k0 = 0; k0 < KP; k0 += 16) {
#pragma unroll
        for (int e2 = 0; e2 < 2; e2++) {
            int e = t * 2 + e2;
            int r = e >> 2, c4 = e & 3;
            float4 f = *(const float4*)(A + (bRow + r) * KP + k0 + c4 * 4);
            As[c4 * 4 + 0][r] = f.x; As[c4 * 4 + 1][r] = f.y;
            As[c4 * 4 + 2][r] = f.z; As[c4 * 4 + 3][r] = f.w;
        }
#pragma unroll
        for (int e2 = 0; e2 < 2; e2++) {
            int e = t * 2 + e2;
            int r = e >> 5, c4 = e & 31;
            *(float4*)&Bs[r][c4 * 4] =
                *(const float4*)(B + (size_t)(k0 + r) * ldb + bCol + c4 * 4);
        }
        __syncthreads();
#pragma unroll
        for (int kk = 0; kk < 16; kk++) {
            longlong2 bb0 = *(const longlong2*)&Bs[kk][tx * 8];
            longlong2 bb1 = *(const longlong2*)&Bs[kk][tx * 8 + 4];
            u64 b[4] = { (u64)bb0.x, (u64)bb0.y, (u64)bb1.x, (u64)bb1.y };
            float4 a03 = *(const float4*)&As[kk][ty * 8];
            float4 a47 = *(const float4*)&As[kk][ty * 8 + 4];
            float a[8] = { a03.x, a03.y, a03.z, a03.w, a47.x, a47.y, a47.z, a47.w };
#pragma unroll
            for (int i = 0; i < 8; i++) {
                u64 aa = pk(a[i], a[i]);
#pragma unroll
                for (int p = 0; p < 4; p++) acc[i][p] = fma2(aa, b[p], acc[i][p]);
            }
        }
        __syncthreads();
    }
#pragma unroll
    for (int i = 0; i < 8; i++) {
        float* cr = C + (bRow + ty * 8 + i) * (size_t)ldc + bCol + tx * 8;
#pragma unroll
        for (int p = 0; p < 4; p++) {
            float lo, hi; upk(lo, hi, acc[i][p]);
            ((float2*)cr)[p] = make_float2(fmaxf(lo, 0.f), fmaxf(hi, 0.f));
        }
    }
}

// ---------------- masked max-pool over compacted rows ----------------------
__global__ void __launch_bounds__(256) pool_kernel(float* __restrict__ out) {
    int c = blockIdx.x, j = threadIdx.x;
    int off = g_off[c], cnt = g_cnt[c];
    float acc = 0.0f;
    if (cnt > 0) {
        acc = g_H3[(size_t)off * 256 + j];
        for (int s = 1; s < cnt; s++)
            acc = fmaxf(acc, g_H3[(size_t)(off + s) * 256 + j]);
    }
    out[(size_t)c * 256 + j] = acc;
}

// ---------------- launcher ----------------------------------------------
extern "C" void kernel_launch(void* const* d_in, const int* in_sizes, int n_in,
                              void* d_out, int out_size) {
    const float* x  = (const float*)d_in[0];
    const float* W1 = (const float*)d_in[1];
    const float* b1 = (const float*)d_in[2];
    const float* W2 = (const float*)d_in[3];
    const float* b2 = (const float*)d_in[4];
    const float* W3 = (const float*)d_in[5];
    const float* b3 = (const float*)d_in[6];
    float* out = (float*)d_out;

    cudaFuncSetAttribute(fps_kernel, cudaFuncAttributeMaxDynamicSharedMemorySize,
                         FPS_SMEM_BYTES);
    cudaFuncSetAttribute(knn_kernel, cudaFuncAttributeMaxDynamicSharedMemorySize,
                         KNN_SMEM_BYTES);

    prep_kernel<<<144, 256>>>(x, W1, b1, W2, b2, W3, b3);
    fps_kernel<<<CLSZ, 256, FPS_SMEM_BYTES>>>();
    knn_kernel<<<M_CTR / KNC, 512, KNN_SMEM_BYTES>>>();
    scan_kernel<<<1, 512>>>();
    rowmap_kernel<<<NROWS / 256, 256>>>();
    gather_kernel<<<512, 256>>>(x);
    sgemm_kernel<0><<<dim3(NROWS / 128, 1), 256>>>();
    sgemm_kernel<1><<<dim3(NROWS / 128, 1), 256>>>();
    sgemm_kernel<2><<<dim3(NROWS / 128, 2), 256>>>();
    pool_kernel<<<M_CTR, 256>>>(out);
}

// round 14
// speedup vs baseline: 1.1716x; 1.0014x over previous
#include <cuda_runtime.h>
#include <cuda_bf16.h>
#include <cstdint>

typedef unsigned long long u64;

#define N_PTS 16384
#define M_CTR 4096
#define NNB   32
#define R2F   0.04f
#define NROWS (M_CTR*NNB)
#define KP    144
#define CAP   256
#define CLSZ  8               // FPS cluster size
#define PPC   (N_PTS/CLSZ)    // 2048 points per CTA
#define FPT   8               // points per thread (256 thr/CTA)
#define NSLOT 64              // 8 CTAs x 8 warps
#define KNC   16              // centers per knn CTA

// ---------------- device scratch ----------------------------------------
__device__ __align__(16) float4 g_pos4[N_PTS];
__device__ __align__(16) float4 g_center[M_CTR];
__device__ int   g_cols[NROWS];
__device__ int   g_cnt[M_CTR];
__device__ int   g_off[M_CTR];
__device__ int   g_nv;
__device__ int   g_rows[NROWS];
__device__ __align__(16) float g_W1p[KP*128];
__device__ __align__(16) float g_W2p[KP*128];
__device__ __align__(16) float g_W3p[KP*256];
__device__ __align__(16) float g_A [(size_t)NROWS*KP];
__device__ __align__(16) float g_H1[(size_t)NROWS*KP];
__device__ __align__(16) float g_H2[(size_t)NROWS*KP];
__device__ __align__(16) float g_H3[(size_t)NROWS*256];

// ---------------- f32x2 helpers -----------------------------------------
__device__ __forceinline__ u64 pk(float lo, float hi) {
    u64 r; asm("mov.b64 %0,{%1,%2};" : "=l"(r) : "f"(lo), "f"(hi)); return r;
}
__device__ __forceinline__ void upk(float& lo, float& hi, u64 v) {
    asm("mov.b64 {%0,%1},%2;" : "=f"(lo), "=f"(hi) : "l"(v));
}
__device__ __forceinline__ u64 add2(u64 a, u64 b) {
    u64 r; asm("add.rn.f32x2 %0,%1,%2;" : "=l"(r) : "l"(a), "l"(b)); return r;
}
__device__ __forceinline__ u64 mul2(u64 a, u64 b) {
    u64 r; asm("mul.rn.f32x2 %0,%1,%2;" : "=l"(r) : "l"(a), "l"(b)); return r;
}
__device__ __forceinline__ u64 fma2(u64 a, u64 b, u64 c) {
    u64 r; asm("fma.rn.f32x2 %0,%1,%2,%3;" : "=l"(r) : "l"(a), "l"(b), "l"(c)); return r;
}

// ---------------- cluster / mbarrier PTX helpers -------------------------
__device__ __forceinline__ unsigned sh_u32(const void* p) {
    return (unsigned)__cvta_generic_to_shared(p);
}
__device__ __forceinline__ unsigned mapa_sh(unsigned addr, unsigned rank) {
    unsigned r;
    asm("mapa.shared::cluster.u32 %0, %1, %2;" : "=r"(r) : "r"(addr), "r"(rank));
    return r;
}
__device__ __forceinline__ void mbar_init(unsigned a, unsigned cnt) {
    asm volatile("mbarrier.init.shared.b64 [%0], %1;" :: "r"(a), "r"(cnt) : "memory");
}
__device__ __forceinline__ void mbar_expect_tx(unsigned a, unsigned bytes) {
    asm volatile("mbarrier.arrive.expect_tx.shared::cta.b64 _, [%0], %1;"
                 :: "r"(a), "r"(bytes) : "memory");
}
__device__ __forceinline__ void st_async_u64(unsigned a, u64 v, unsigned mbar) {
    asm volatile("st.async.shared::cluster.mbarrier::complete_tx::bytes.b64 [%0], %1, [%2];"
                 :: "r"(a), "l"(v), "r"(mbar) : "memory");
}
__device__ __forceinline__ u64 ld_vol_sh_u64(unsigned a) {
    u64 r; asm volatile("ld.volatile.shared.u64 %0, [%1];" : "=l"(r) : "r"(a));
    return r;
}
__device__ __forceinline__ void cluster_sync_all() {
    asm volatile("barrier.cluster.arrive.aligned;" ::: "memory");
    asm volatile("barrier.cluster.wait.aligned;" ::: "memory");
}
__device__ __forceinline__ unsigned redux_max_u32(unsigned v) {
    unsigned r;
    asm("redux.sync.max.u32 %0, %1, 0xffffffff;" : "=r"(r) : "r"(v));
    return r;
}

// ---------------- prep ----------------------------------------------------
__global__ void __launch_bounds__(256) prep_kernel(
    const float* __restrict__ x,
    const float* __restrict__ W1, const float* __restrict__ b1,
    const float* __restrict__ W2, const float* __restrict__ b2,
    const float* __restrict__ W3, const float* __restrict__ b3)
{
    int i = blockIdx.x * 256 + threadIdx.x;
    if (i < N_PTS) {
        const float* row = x + (size_t)i * 131;
        g_pos4[i] = make_float4(row[0], row[1], row[2], 0.f);
    }
    if (i < KP * 128) {
        int k = i >> 7, j = i & 127;
        g_W1p[i] = (k < 131) ? W1[k * 128 + j] : (k == 131 ? b1[j] : 0.f);
        g_W2p[i] = (k < 128) ? W2[k * 128 + j] : (k == 128 ? b2[j] : 0.f);
    }
    if (i < KP * 256) {
        int k = i >> 8, j = i & 255;
        g_W3p[i] = (k < 128) ? W3[k * 256 + j] : (k == 128 ? b3[j] : 0.f);
    }
}

// ---------------- FPS: 8 CTAs x 256 thr, tag-polled key exchange -----------
// Key low32 = (stepTag<<24) | 0x3FF<<14 | (~oidx & 0x3FFF). Tag/const bits
// are equal across all senders in a step, so u64-max ordering (value,
// tie -> min idx) is bit-identical to prior rounds. Receivers spin on
// volatile loads until all 64 slots carry the current tag (no mbarrier wait).
#define FPS_SMEM_BYTES (3 * N_PTS * 4)    // s_px/s_py/s_pz = 192KB

__global__ void __launch_bounds__(256, 1) __cluster_dims__(CLSZ, 1, 1)
fps_kernel() {
    extern __shared__ float s_dyn[];
    float* s_px = s_dyn;
    float* s_py = s_dyn + N_PTS;
    float* s_pz = s_dyn + 2 * N_PTS;
    __shared__ __align__(16) u64 s_mbk[2][NSLOT];   // 64 warp-best keys
    __shared__ __align__(8)  u64 s_bar[2];

    int tid = threadIdx.x, lane = tid & 31, warp = tid >> 5;
    unsigned rank;
    asm("mov.u32 %0, %%cluster_ctarank;" : "=r"(rank));
    int pbase = (int)rank * PPC + tid;
    int slotid = (int)rank * 8 + warp;              // my warp's mailbox slot

    // full position replica in smem (one-time)
    for (int i = tid; i < N_PTS; i += 256) {
        float4 p = g_pos4[i];
        s_px[i] = p.x; s_py[i] = p.y; s_pz[i] = p.z;
    }
    // zero mailbox (tag field 0 != any step tag at first uses)
    if (tid < NSLOT) { s_mbk[0][tid] = 0ull; s_mbk[1][tid] = 0ull; }

    // own-shard coords register-resident; min_d as u32 bits
    u64 PX[4], PY[4], PZ[4];
    unsigned mb[FPT];
    unsigned nlo[FPT];                              // ~oidx, loop-invariant
#pragma unroll
    for (int q = 0; q < 4; q++) {
        float4 a = g_pos4[pbase + (2 * q) * 256];
        float4 b = g_pos4[pbase + (2 * q + 1) * 256];
        PX[q] = pk(a.x, b.x); PY[q] = pk(a.y, b.y); PZ[q] = pk(a.z, b.z);
        mb[2 * q] = 0x7f800000u;
        mb[2 * q + 1] = 0x7f800000u;
    }
#pragma unroll
    for (int i = 0; i < FPT; i++) nlo[i] = ~(unsigned)(pbase + i * 256);

    if (tid == 0) {
        mbar_init(sh_u32(&s_bar[0]), 1);   // tx bookkeeping only (never waited)
        mbar_init(sh_u32(&s_bar[1]), 1);
    }
    // hoisted remote addresses for sending lanes (dst = lane&7)
    unsigned dst = (unsigned)(lane & 7);
    unsigned rab0 = mapa_sh(sh_u32(&s_bar[0]), dst);
    unsigned rab1 = mapa_sh(sh_u32(&s_bar[1]), dst);
    unsigned rak0 = mapa_sh(sh_u32(&s_mbk[0][slotid]), dst);
    unsigned rak1 = mapa_sh(sh_u32(&s_mbk[1][slotid]), dst);
    // local slot addresses for polling
    unsigned pa1[2], pa2[2];
    pa1[0] = sh_u32(&s_mbk[0][lane]);      pa1[1] = sh_u32(&s_mbk[1][lane]);
    pa2[0] = sh_u32(&s_mbk[0][lane + 32]); pa2[1] = sh_u32(&s_mbk[1][lane + 32]);

    __syncthreads();
    cluster_sync_all();     // mailbox zeros + replica visible before any send

    float4 c0 = g_pos4[0];
    float cx = c0.x, cy = c0.y, cz = c0.z;
    if (rank == 0 && tid == 0) g_center[0] = make_float4(cx, cy, cz, 0.f);

    for (int k = 1; k < M_CTR; k++) {
        int buf = k & 1;
        unsigned tagk = (unsigned)k & 0xFFu;
        // balance tx-counts (never waited on; off critical path)
        if (tid == 0) mbar_expect_tx(sh_u32(&s_bar[buf]), NSLOT * 8);

        // --- packed exact distance update (rn ops, (x2+y2)+z2, p+(-c)) ---
        u64 ncx = pk(-cx, -cx), ncy = pk(-cy, -cy), ncz = pk(-cz, -cz);
#pragma unroll
        for (int q = 0; q < 4; q++) {
            u64 dx = add2(PX[q], ncx);
            u64 dy = add2(PY[q], ncy);
            u64 dz = add2(PZ[q], ncz);
            u64 s  = add2(add2(mul2(dx, dx), mul2(dy, dy)), mul2(dz, dz));
            float d0, d1; upk(d0, d1, s);
            mb[2 * q]     = min(mb[2 * q],     __float_as_uint(d0));
            mb[2 * q + 1] = min(mb[2 * q + 1], __float_as_uint(d1));
        }
        // --- per-thread select: direct u64 key max (tie -> min oidx) ------
        u64 key = ((u64)mb[0] << 32) | nlo[0];
#pragma unroll
        for (int i = 1; i < FPT; i++) {
            u64 ki = ((u64)mb[i] << 32) | nlo[i];
            if (ki > key) key = ki;
        }
        // --- warp argmax via redux (keys only) ----------------------------
        u64 kbest;
        {
            unsigned vb = (unsigned)(key >> 32);
            unsigned mx = redux_max_u32(vb);
            unsigned cand = (vb == mx) ? (unsigned)key : 0u;
            unsigned lw = redux_max_u32(cand);
            kbest = ((u64)mx << 32) | lw;
        }
        // --- lanes 0..7 send tagged warp-best to all CTAs ------------------
        if (lane < CLSZ) {
            unsigned lowm = (tagk << 24) | 0x00FFC000u | ((unsigned)kbest & 0x3FFFu);
            u64 sv = (kbest & 0xFFFFFFFF00000000ull) | (u64)lowm;
            st_async_u64(buf ? rak1 : rak0, sv, buf ? rab1 : rab0);
        }
        // --- poll slots until all carry current tag, pick winner ----------
        {
            unsigned a1 = pa1[buf], a2 = pa2[buf];
            unsigned want = tagk << 24;
            u64 k1, k2;
            while (true) {
                k1 = ld_vol_sh_u64(a1);
                k2 = ld_vol_sh_u64(a2);
                bool f = ((((unsigned)k1 ^ want) & 0xFF000000u) == 0u) &&
                         ((((unsigned)k2 ^ want) & 0xFF000000u) == 0u);
                if (__all_sync(0xffffffffu, f)) break;
            }
            u64 kk = (k2 > k1) ? k2 : k1;
            unsigned vb = (unsigned)(kk >> 32);
            unsigned mx = redux_max_u32(vb);
            unsigned cand = (vb == mx) ? (unsigned)kk : 0u;
            unsigned lw = redux_max_u32(cand);
            int oidx = (int)((~lw) & 0x3FFFu);       // winner point index
            cx = s_px[oidx]; cy = s_py[oidx]; cz = s_pz[oidx];  // broadcast LDS
        }
        if (rank == 0 && tid == 0) g_center[k] = make_float4(cx, cy, cz, 0.f);
    }
    cluster_sync_all();
}

// ---------------- radius-KNN: 16 centers per CTA share tiles ---------------
#define KNN_SMEM_BYTES (65536 + KNC * CAP * 8)      // tiles 64KB + lists 32KB

__global__ void __launch_bounds__(512) knn_kernel() {
    extern __shared__ char sm_raw[];
    float4* s_t   = (float4*)sm_raw;                 // 4096 float4 = 64KB
    u64*    s_lst = (u64*)(sm_raw + 65536);          // KNC x CAP keys
    int tid = threadIdx.x, lane = tid & 31, warp = tid >> 5;
    int c = blockIdx.x * KNC + warp;
    u64* lst = s_lst + warp * CAP;
    float4 ct = g_center[c];

    int cnt = 0;
    for (int tile = 0; tile < 4; tile++) {
        __syncthreads();
        for (int i = tid; i < 4096; i += 512) s_t[i] = g_pos4[tile * 4096 + i];
        __syncthreads();
        for (int i = lane; i < 4096; i += 32) {
            float4 p = s_t[i];
            float dx = __fsub_rn(ct.x, p.x);
            float dy = __fsub_rn(ct.y, p.y);
            float dz = __fsub_rn(ct.z, p.z);
            float d2 = __fadd_rn(__fadd_rn(__fmul_rn(dx, dx), __fmul_rn(dy, dy)),
                                 __fmul_rn(dz, dz));
            bool ok = d2 <= R2F;
            unsigned mk = __ballot_sync(0xffffffffu, ok);
            if (ok) {
                int pos = cnt + __popc(mk & ((1u << lane) - 1u));
                if (pos < CAP)
                    lst[pos] = ((u64)__float_as_uint(d2) << 32)
                               | (unsigned)(tile * 4096 + i);
            }
            cnt += __popc(mk);
        }
    }
    if (cnt > CAP) cnt = CAP;
    __syncwarp();

    if (cnt <= NNB) {
        int v = (lane < cnt) ? (int)(unsigned)(lst[lane] & 0xffffffffu) : -1;
        g_cols[c * NNB + lane] = v;
        if (lane == 0) g_cnt[c] = cnt;
    } else {
        for (int i = lane; i < cnt; i += 32) {
            u64 ki = lst[i];
            int rnk = 0;
            for (int j = 0; j < cnt; j++) rnk += (lst[j] < ki);
            if (rnk < NNB)
                g_cols[c * NNB + rnk] = (int)(unsigned)(ki & 0xffffffffu);
        }
        if (lane == 0) g_cnt[c] = NNB;
    }
}

// ---------------- exclusive scan of g_cnt (ENV CANARY — DO NOT TOUCH) ------
__global__ void __launch_bounds__(512, 1) scan_kernel() {
    __shared__ int s_ws[16];
    int tid = threadIdx.x, lane = tid & 31, warp = tid >> 5;
    int v[8], run = 0;
#pragma unroll
    for (int i = 0; i < 8; i++) { v[i] = g_cnt[tid * 8 + i]; run += v[i]; }
    int tot = run;
    int pre = tot;
#pragma unroll
    for (int o = 1; o < 32; o <<= 1) {
        int t = __shfl_up_sync(0xffffffffu, pre, o);
        if (lane >= o) pre += t;
    }
    if (lane == 31) s_ws[warp] = pre;
    int excl = pre - tot;
    __syncthreads();
    if (warp == 0) {
        int w = (lane < 16) ? s_ws[lane] : 0;
#pragma unroll
        for (int o = 1; o < 16; o <<= 1) {
            int t = __shfl_up_sync(0xffffffffu, w, o);
            if (lane >= o) w += t;
        }
        if (lane < 16) s_ws[lane] = w;
    }
    __syncthreads();
    int base = (warp > 0) ? s_ws[warp - 1] : 0;
    int off = base + excl;
#pragma unroll
    for (int i = 0; i < 8; i++) { g_off[tid * 8 + i] = off; off += v[i]; }
    if (tid == 511) g_nv = off;
}

// ---------------- row map: compacted row -> (center,slot) ------------------
__global__ void __launch_bounds__(256) rowmap_kernel() {
    int idx = blockIdx.x * 256 + threadIdx.x;
    int c = idx >> 5, s = idx & 31;
    if (s < g_cnt[c]) g_rows[g_off[c] + s] = idx;
}

// ---------------- gather + bias-pad (compacted rows only) ------------------
__global__ void __launch_bounds__(256) gather_kernel(const float* __restrict__ x) {
    int lane = threadIdx.x & 31;
    int warp = threadIdx.x >> 5;
    int nv = g_nv;
    float4 one0 = make_float4(1.f, 0.f, 0.f, 0.f);
    float4 z    = make_float4(0.f, 0.f, 0.f, 0.f);
    for (int r = blockIdx.x * 8 + warp; r < nv; r += 512 * 8) {
        int rid = g_rows[r];
        int c   = rid >> 5;
        int col = g_cols[rid];
        float* a = g_A + (size_t)r * KP;
        const float* xr = x + (size_t)col * 131 + 3 + 4 * lane;
        ((float4*)a)[lane] = make_float4(xr[0], xr[1], xr[2], xr[3]);
        if (lane < 4) {                      // A pad cols 128..143
            float4 e = z;
            if (lane == 0) {
                float4 p = g_pos4[col]; float4 ct = g_center[c];
                e = make_float4(p.x - ct.x, p.y - ct.y, p.z - ct.z, 1.0f);
            }
            ((float4*)a)[32 + lane] = e;
        } else if (lane < 8) {               // H1 bias cols
            ((float4*)(g_H1 + (size_t)r * KP + 128))[lane - 4] =
                (lane == 4) ? one0 : z;
        } else if (lane < 12) {              // H2 bias cols
            ((float4*)(g_H2 + (size_t)r * KP + 128))[lane - 8] =
                (lane == 8) ? one0 : z;
        }
    }
}

// ---------------- tiled fp32 GEMM + relu (early-exit past NV) --------------
template<int L>
__global__ void __launch_bounds__(256) sgemm_kernel() {
    size_t bRow = (size_t)blockIdx.x * 128;
    if ((int)bRow >= g_nv) return;
    const float* A = (L == 0) ? g_A  : (L == 1) ? g_H1 : g_H2;
    const float* B = (L == 0) ? g_W1p : (L == 1) ? g_W2p : g_W3p;
    float*       C = (L == 0) ? g_H1 : (L == 1) ? g_H2 : g_H3;
    const int ldb = (L == 2) ? 256 : 128;
    const int ldc = (L == 2) ? 256 : KP;

    __shared__ __align__(16) float As[16][132];
    __shared__ __align__(16) float Bs[16][132];
    int t  = threadIdx.x;
    int tx = t & 15, ty = t >> 4;
    int    bCol = blockIdx.y * 128;

    u64 acc[8][4];
#pragma unroll
    for (int i = 0; i < 8; i++)
#pragma unroll
        for (int p = 0; p < 4; p++) acc[i][p] = 0ull;

    for (int k0 = 0; k0 < KP; k0 += 16) {
#pragma unroll
        for (int e2 = 0; e2 < 2; e2++) {
            int e = t * 2 + e2;
            int r = e >> 2, c4 = e & 3;
            float4 f = *(const float4*)(A + (bRow + r) * KP + k0 + c4 * 4);
            As[c4 * 4 + 0][r] = f.x; As[c4 * 4 + 1][r] = f.y;
            As[c4 * 4 + 2][r] = f.z; As[c4 * 4 + 3][r] = f.w;
        }
#pragma unroll
        for (int e2 = 0; e2 < 2; e2++) {
            int e = t * 2 + e2;
            int r = e >> 5, c4 = e & 31;
            *(float4*)&Bs[r][c4 * 4] =
                *(const float4*)(B + (size_t)(k0 + r) * ldb + bCol + c4 * 4);
        }
        __syncthreads();
#pragma unroll
        for (int kk = 0; kk < 16; kk++) {
            longlong2 bb0 = *(const longlong2*)&Bs[kk][tx * 8];
            longlong2 bb1 = *(const longlong2*)&Bs[kk][tx * 8 + 4];
            u64 b[4] = { (u64)bb0.x, (u64)bb0.y, (u64)bb1.x, (u64)bb1.y };
            float4 a03 = *(const float4*)&As[kk][ty * 8];
            float4 a47 = *(const float4*)&As[kk][ty * 8 + 4];
            float a[8] = { a03.x, a03.y, a03.z, a03.w, a47.x, a47.y, a47.z, a47.w };
#pragma unroll
            for (int i = 0; i < 8; i++) {
                u64 aa = pk(a[i], a[i]);
#pragma unroll
                for (int p = 0; p < 4; p++) acc[i][p] = fma2(aa, b[p], acc[i][p]);
            }
        }
        __syncthreads();
    }
#pragma unroll
    for (int i = 0; i < 8; i++) {
        float* cr = C + (bRow + ty * 8 + i) * (size_t)ldc + bCol + tx * 8;
#pragma unroll
        for (int p = 0; p < 4; p++) {
            float lo, hi; upk(lo, hi, acc[i][p]);
            ((float2*)cr)[p] = make_float2(fmaxf(lo, 0.f), fmaxf(hi, 0.f));
        }
    }
}

// ---------------- masked max-pool over compacted rows ----------------------
__global__ void __launch_bounds__(256) pool_kernel(float* __restrict__ out) {
    int c = blockIdx.x, j = threadIdx.x;
    int off = g_off[c], cnt = g_cnt[c];
    float acc = 0.0f;
    if (cnt > 0) {
        acc = g_H3[(size_t)off * 256 + j];
        for (int s = 1; s < cnt; s++)
            acc = fmaxf(acc, g_H3[(size_t)(off + s) * 256 + j]);
    }
    out[(size_t)c * 256 + j] = acc;
}

// ---------------- launcher ----------------------------------------------
extern "C" void kernel_launch(void* const* d_in, const int* in_sizes, int n_in,
                              void* d_out, int out_size) {
    const float* x  = (const float*)d_in[0];
    const float* W1 = (const float*)d_in[1];
    const float* b1 = (const float*)d_in[2];
    const float* W2 = (const float*)d_in[3];
    const float* b2 = (const float*)d_in[4];
    const float* W3 = (const float*)d_in[5];
    const float* b3 = (const float*)d_in[6];
    float* out = (float*)d_out;

    cudaFuncSetAttribute(fps_kernel, cudaFuncAttributeMaxDynamicSharedMemorySize,
                         FPS_SMEM_BYTES);
    cudaFuncSetAttribute(knn_kernel, cudaFuncAttributeMaxDynamicSharedMemorySize,
                         KNN_SMEM_BYTES);

    prep_kernel<<<144, 256>>>(x, W1, b1, W2, b2, W3, b3);
    fps_kernel<<<CLSZ, 256, FPS_SMEM_BYTES>>>();
    knn_kernel<<<M_CTR / KNC, 512, KNN_SMEM_BYTES>>>();
    scan_kernel<<<1, 512>>>();
    rowmap_kernel<<<NROWS / 256, 256>>>();
    gather_kernel<<<512, 256>>>(x);
    sgemm_kernel<0><<<dim3(NROWS / 128, 1), 256>>>();
    sgemm_kernel<1><<<dim3(NROWS / 128, 1), 256>>>();
    sgemm_kernel<2><<<dim3(NROWS / 128, 2), 256>>>();
    pool_kernel<<<M_CTR, 256>>>(out);
}

// round 15
// speedup vs baseline: 1.1973x; 1.0220x over previous
#include <cuda_runtime.h>
#include <cuda_bf16.h>
#include <cstdint>

typedef unsigned long long u64;

#define N_PTS 16384
#define M_CTR 4096
#define NNB   32
#define R2F   0.04f
#define NROWS (M_CTR*NNB)
#define KP    144
#define CAP   256
#define CLSZ  8               // FPS cluster size
#define PPC   (N_PTS/CLSZ)    // 2048 points per CTA
#define FPT   8               // points per thread (256 thr/CTA)
#define NSLOT 128             // 8 CTAs x 8 warps x top-2
#define KNC   16              // centers per knn CTA

// ---------------- device scratch ----------------------------------------
__device__ __align__(16) float4 g_pos4[N_PTS];
__device__ __align__(16) float4 g_center[M_CTR];
__device__ int   g_cols[NROWS];
__device__ int   g_cnt[M_CTR];
__device__ int   g_off[M_CTR];
__device__ int   g_nv;
__device__ int   g_rows[NROWS];
__device__ __align__(16) float g_W1p[KP*128];
__device__ __align__(16) float g_W2p[KP*128];
__device__ __align__(16) float g_W3p[KP*256];
__device__ __align__(16) float g_A [(size_t)NROWS*KP];
__device__ __align__(16) float g_H1[(size_t)NROWS*KP];
__device__ __align__(16) float g_H2[(size_t)NROWS*KP];
__device__ __align__(16) float g_H3[(size_t)NROWS*256];

// ---------------- f32x2 helpers -----------------------------------------
__device__ __forceinline__ u64 pk(float lo, float hi) {
    u64 r; asm("mov.b64 %0,{%1,%2};" : "=l"(r) : "f"(lo), "f"(hi)); return r;
}
__device__ __forceinline__ void upk(float& lo, float& hi, u64 v) {
    asm("mov.b64 {%0,%1},%2;" : "=f"(lo), "=f"(hi) : "l"(v));
}
__device__ __forceinline__ u64 add2(u64 a, u64 b) {
    u64 r; asm("add.rn.f32x2 %0,%1,%2;" : "=l"(r) : "l"(a), "l"(b)); return r;
}
__device__ __forceinline__ u64 mul2(u64 a, u64 b) {
    u64 r; asm("mul.rn.f32x2 %0,%1,%2;" : "=l"(r) : "l"(a), "l"(b)); return r;
}
__device__ __forceinline__ u64 fma2(u64 a, u64 b, u64 c) {
    u64 r; asm("fma.rn.f32x2 %0,%1,%2,%3;" : "=l"(r) : "l"(a), "l"(b), "l"(c)); return r;
}

// ---------------- cluster / mbarrier PTX helpers -------------------------
__device__ __forceinline__ unsigned sh_u32(const void* p) {
    return (unsigned)__cvta_generic_to_shared(p);
}
__device__ __forceinline__ unsigned mapa_sh(unsigned addr, unsigned rank) {
    unsigned r;
    asm("mapa.shared::cluster.u32 %0, %1, %2;" : "=r"(r) : "r"(addr), "r"(rank));
    return r;
}
__device__ __forceinline__ void mbar_init(unsigned a, unsigned cnt) {
    asm volatile("mbarrier.init.shared.b64 [%0], %1;" :: "r"(a), "r"(cnt) : "memory");
}
__device__ __forceinline__ void mbar_expect_tx(unsigned a, unsigned bytes) {
    asm volatile("mbarrier.arrive.expect_tx.shared::cta.b64 _, [%0], %1;"
                 :: "r"(a), "r"(bytes) : "memory");
}
__device__ __forceinline__ void st_async_u64(unsigned a, u64 v, unsigned mbar) {
    asm volatile("st.async.shared::cluster.mbarrier::complete_tx::bytes.b64 [%0], %1, [%2];"
                 :: "r"(a), "l"(v), "r"(mbar) : "memory");
}
__device__ __forceinline__ u64 ld_vol_sh_u64(unsigned a) {
    u64 r; asm volatile("ld.volatile.shared.u64 %0, [%1];" : "=l"(r) : "r"(a));
    return r;
}
__device__ __forceinline__ void cluster_sync_all() {
    asm volatile("barrier.cluster.arrive.aligned;" ::: "memory");
    asm volatile("barrier.cluster.wait.aligned;" ::: "memory");
}
__device__ __forceinline__ unsigned redux_max_u32(unsigned v) {
    unsigned r;
    asm("redux.sync.max.u32 %0, %1, 0xffffffff;" : "=r"(r) : "r"(v));
    return r;
}
// warp-wide exact u64 key max via two redux rounds (keys unique)
__device__ __forceinline__ u64 warp_max_key(u64 key) {
    unsigned vb = (unsigned)(key >> 32);
    unsigned mx = redux_max_u32(vb);
    unsigned cand = (vb == mx) ? (unsigned)key : 0u;
    unsigned lw = redux_max_u32(cand);
    return ((u64)mx << 32) | lw;
}

// ---------------- prep ----------------------------------------------------
__global__ void __launch_bounds__(256) prep_kernel(
    const float* __restrict__ x,
    const float* __restrict__ W1, const float* __restrict__ b1,
    const float* __restrict__ W2, const float* __restrict__ b2,
    const float* __restrict__ W3, const float* __restrict__ b3)
{
    int i = blockIdx.x * 256 + threadIdx.x;
    if (i < N_PTS) {
        const float* row = x + (size_t)i * 131;
        g_pos4[i] = make_float4(row[0], row[1], row[2], 0.f);
    }
    if (i < KP * 128) {
        int k = i >> 7, j = i & 127;
        g_W1p[i] = (k < 131) ? W1[k * 128 + j] : (k == 131 ? b1[j] : 0.f);
        g_W2p[i] = (k < 128) ? W2[k * 128 + j] : (k == 128 ? b2[j] : 0.f);
    }
    if (i < KP * 256) {
        int k = i >> 8, j = i & 255;
        g_W3p[i] = (k < 128) ? W3[k * 256 + j] : (k == 128 ? b3[j] : 0.f);
    }
}

// ---------------- FPS: 8 CTAs x 256 thr, top-2 exchange + exact pairing ----
// Per exchange each warp sends its top-2 keys (128 tagged slots). Receivers
// compute global w = max, r = max excluding w. If d(r,w) >= min_d(r) (exact
// rn math, evaluated identically on all CTAs), r is PROVABLY the next winner
// (all other keys can only decrease, keys unique), so two centers are
// consumed per exchange. Bit-identical to sequential reference.
#define FPS_SMEM_BYTES (3 * N_PTS * 4)    // s_px/s_py/s_pz = 192KB

__global__ void __launch_bounds__(256, 1) __cluster_dims__(CLSZ, 1, 1)
fps_kernel() {
    extern __shared__ float s_dyn[];
    float* s_px = s_dyn;
    float* s_py = s_dyn + N_PTS;
    float* s_pz = s_dyn + 2 * N_PTS;
    __shared__ __align__(16) u64 s_mbk[2][NSLOT];   // [0..63] top1, [64..127] top2
    __shared__ __align__(8)  u64 s_bar[2];

    int tid = threadIdx.x, lane = tid & 31, warp = tid >> 5;
    unsigned rank;
    asm("mov.u32 %0, %%cluster_ctarank;" : "=r"(rank));
    int pbase = (int)rank * PPC + tid;
    int slotid = (int)rank * 8 + warp;

    // full position replica in smem (one-time)
    for (int i = tid; i < N_PTS; i += 256) {
        float4 p = g_pos4[i];
        s_px[i] = p.x; s_py[i] = p.y; s_pz[i] = p.z;
    }
    // zero mailbox (tag field 0; exchange tags start at 1)
    if (tid < NSLOT) { s_mbk[0][tid] = 0ull; s_mbk[1][tid] = 0ull; }

    // own-shard coords register-resident; min_d as u32 bits
    u64 PX[4], PY[4], PZ[4];
    unsigned mb[FPT];
    unsigned nlo[FPT];                              // ~oidx, loop-invariant
#pragma unroll
    for (int q = 0; q < 4; q++) {
        float4 a = g_pos4[pbase + (2 * q) * 256];
        float4 b = g_pos4[pbase + (2 * q + 1) * 256];
        PX[q] = pk(a.x, b.x); PY[q] = pk(a.y, b.y); PZ[q] = pk(a.z, b.z);
        mb[2 * q] = 0x7f800000u;
        mb[2 * q + 1] = 0x7f800000u;
    }
#pragma unroll
    for (int i = 0; i < FPT; i++) nlo[i] = ~(unsigned)(pbase + i * 256);

    if (tid == 0) {
        mbar_init(sh_u32(&s_bar[0]), 1);   // tx bookkeeping only (never waited)
        mbar_init(sh_u32(&s_bar[1]), 1);
    }
    // send addresses: lanes 0..7 carry warp-top1, lanes 8..15 warp-top2
    unsigned dst = (unsigned)(lane & 7);
    int slotbase = (lane < 8) ? slotid : (64 + slotid);
    unsigned rab0 = mapa_sh(sh_u32(&s_bar[0]), dst);
    unsigned rab1 = mapa_sh(sh_u32(&s_bar[1]), dst);
    unsigned rak0 = mapa_sh(sh_u32(&s_mbk[0][slotbase]), dst);
    unsigned rak1 = mapa_sh(sh_u32(&s_mbk[1][slotbase]), dst);
    // poll addresses (each warp covers all 128 slots: lane + 32*j)
    unsigned pa[2][4];
#pragma unroll
    for (int b = 0; b < 2; b++)
#pragma unroll
        for (int j = 0; j < 4; j++)
            pa[b][j] = sh_u32(&s_mbk[b][lane + 32 * j]);

    __syncthreads();
    cluster_sync_all();     // mailbox zeros + replica visible before any send

    float4 c0 = g_pos4[0];
    float cx = c0.x, cy = c0.y, cz = c0.z;       // pending center 1
    float prx = 0.f, pry = 0.f, prz = 0.f;       // pending center 2 (if pair)
    int pair = 0;
    if (rank == 0 && tid == 0) g_center[0] = make_float4(cx, cy, cz, 0.f);

    int k = 1;
    unsigned e = 1;                               // exchange counter (tags)
    while (k < M_CTR) {
        int buf = (int)(e & 1u);
        unsigned tagk = e & 0xFFu;
        if (tid == 0) mbar_expect_tx(sh_u32(&s_bar[buf]), NSLOT * 8);

        // --- min_d update with pending center(s); exact reference order ---
        {
            u64 ncx = pk(-cx, -cx), ncy = pk(-cy, -cy), ncz = pk(-cz, -cz);
#pragma unroll
            for (int q = 0; q < 4; q++) {
                u64 dx = add2(PX[q], ncx);
                u64 dy = add2(PY[q], ncy);
                u64 dz = add2(PZ[q], ncz);
                u64 s  = add2(add2(mul2(dx, dx), mul2(dy, dy)), mul2(dz, dz));
                float d0, d1; upk(d0, d1, s);
                mb[2 * q]     = min(mb[2 * q],     __float_as_uint(d0));
                mb[2 * q + 1] = min(mb[2 * q + 1], __float_as_uint(d1));
            }
        }
        if (pair) {
            u64 ncx = pk(-prx, -prx), ncy = pk(-pry, -pry), ncz = pk(-prz, -prz);
#pragma unroll
            for (int q = 0; q < 4; q++) {
                u64 dx = add2(PX[q], ncx);
                u64 dy = add2(PY[q], ncy);
                u64 dz = add2(PZ[q], ncz);
                u64 s  = add2(add2(mul2(dx, dx), mul2(dy, dy)), mul2(dz, dz));
                float d0, d1; upk(d0, d1, s);
                mb[2 * q]     = min(mb[2 * q],     __float_as_uint(d0));
                mb[2 * q + 1] = min(mb[2 * q + 1], __float_as_uint(d1));
            }
        }

        // --- per-thread top-2 keys (tie -> min oidx via ~oidx low bits) ----
        u64 t1 = ((u64)mb[0] << 32) | nlo[0], t2 = 0ull;
#pragma unroll
        for (int i = 1; i < FPT; i++) {
            u64 ki = ((u64)mb[i] << 32) | nlo[i];
            if (ki > t1) { t2 = t1; t1 = ki; }
            else if (ki > t2) t2 = ki;
        }
        // --- warp top-2 via redux -----------------------------------------
        u64 w1 = warp_max_key(t1);
        u64 c2 = (t1 == w1) ? t2 : t1;
        u64 w2 = warp_max_key(c2);

        // --- lanes 0..15 send tagged warp top-2 to all CTAs ----------------
        if (lane < 16) {
            u64 kv = (lane < 8) ? w1 : w2;
            unsigned lowm = (tagk << 24) | 0x00FFC000u | ((unsigned)kv & 0x3FFFu);
            u64 sv = (kv & 0xFFFFFFFF00000000ull) | (u64)lowm;
            st_async_u64(buf ? rak1 : rak0, sv, buf ? rab1 : rab0);
        }

        // --- poll all 128 slots for current tag ---------------------------
        u64 q0, q1, q2, q3;
        {
            unsigned a0 = pa[buf][0], a1 = pa[buf][1], a2 = pa[buf][2], a3 = pa[buf][3];
            unsigned want = tagk << 24;
            while (true) {
                q0 = ld_vol_sh_u64(a0); q1 = ld_vol_sh_u64(a1);
                q2 = ld_vol_sh_u64(a2); q3 = ld_vol_sh_u64(a3);
                bool f = ((((unsigned)q0 ^ want) & 0xFF000000u) == 0u) &&
                         ((((unsigned)q1 ^ want) & 0xFF000000u) == 0u) &&
                         ((((unsigned)q2 ^ want) & 0xFF000000u) == 0u) &&
                         ((((unsigned)q3 ^ want) & 0xFF000000u) == 0u);
                if (__all_sync(0xffffffffu, f)) break;
            }
        }
        // --- global winner w and exact runner-up r -------------------------
        u64 kk = (q1 > q0) ? q1 : q0;
        if (q2 > kk) kk = q2;
        if (q3 > kk) kk = q3;
        u64 wkey = warp_max_key(kk);
        u64 r0 = (q0 == wkey) ? 0ull : q0;
        u64 r1 = (q1 == wkey) ? 0ull : q1;
        u64 r2 = (q2 == wkey) ? 0ull : q2;
        u64 r3 = (q3 == wkey) ? 0ull : q3;
        u64 rc = (r1 > r0) ? r1 : r0;
        if (r2 > rc) rc = r2;
        if (r3 > rc) rc = r3;
        u64 rkey = warp_max_key(rc);

        int widx = (int)((~(unsigned)wkey) & 0x3FFFu);
        int ridx = (int)((~(unsigned)rkey) & 0x3FFFu);
        float wx = s_px[widx], wy = s_py[widx], wz = s_pz[widx];

        // pair condition: d(r,w) >= min_d(r)  (same rn op order as updates)
        float rxc = s_px[ridx], ryc = s_py[ridx], rzc = s_pz[ridx];
        float ddx = __fadd_rn(rxc, -wx);
        float ddy = __fadd_rn(ryc, -wy);
        float ddz = __fadd_rn(rzc, -wz);
        float dd = __fadd_rn(__fadd_rn(__fmul_rn(ddx, ddx), __fmul_rn(ddy, ddy)),
                             __fmul_rn(ddz, ddz));
        bool cond = (__float_as_uint(dd) >= (unsigned)(rkey >> 32));

        // --- consume winner(s) ---------------------------------------------
        cx = wx; cy = wy; cz = wz;
        if (rank == 0 && tid == 0) g_center[k] = make_float4(cx, cy, cz, 0.f);
        if (cond && (k + 1 < M_CTR)) {
            prx = rxc; pry = ryc; prz = rzc;
            if (rank == 0 && tid == 0)
                g_center[k + 1] = make_float4(prx, pry, prz, 0.f);
            pair = 1; k += 2;
        } else {
            pair = 0; k += 1;
        }
        e++;
    }
    cluster_sync_all();
}

// ---------------- radius-KNN: 16 centers per CTA share tiles ---------------
#define KNN_SMEM_BYTES (65536 + KNC * CAP * 8)      // tiles 64KB + lists 32KB

__global__ void __launch_bounds__(512) knn_kernel() {
    extern __shared__ char sm_raw[];
    float4* s_t   = (float4*)sm_raw;                 // 4096 float4 = 64KB
    u64*    s_lst = (u64*)(sm_raw + 65536);          // KNC x CAP keys
    int tid = threadIdx.x, lane = tid & 31, warp = tid >> 5;
    int c = blockIdx.x * KNC + warp;
    u64* lst = s_lst + warp * CAP;
    float4 ct = g_center[c];

    int cnt = 0;
    for (int tile = 0; tile < 4; tile++) {
        __syncthreads();
        for (int i = tid; i < 4096; i += 512) s_t[i] = g_pos4[tile * 4096 + i];
        __syncthreads();
        for (int i = lane; i < 4096; i += 32) {
            float4 p = s_t[i];
            float dx = __fsub_rn(ct.x, p.x);
            float dy = __fsub_rn(ct.y, p.y);
            float dz = __fsub_rn(ct.z, p.z);
            float d2 = __fadd_rn(__fadd_rn(__fmul_rn(dx, dx), __fmul_rn(dy, dy)),
                                 __fmul_rn(dz, dz));
            bool ok = d2 <= R2F;
            unsigned mk = __ballot_sync(0xffffffffu, ok);
            if (ok) {
                int pos = cnt + __popc(mk & ((1u << lane) - 1u));
                if (pos < CAP)
                    lst[pos] = ((u64)__float_as_uint(d2) << 32)
                               | (unsigned)(tile * 4096 + i);
            }
            cnt += __popc(mk);
        }
    }
    if (cnt > CAP) cnt = CAP;
    __syncwarp();

    if (cnt <= NNB) {
        int v = (lane < cnt) ? (int)(unsigned)(lst[lane] & 0xffffffffu) : -1;
        g_cols[c * NNB + lane] = v;
        if (lane == 0) g_cnt[c] = cnt;
    } else {
        for (int i = lane; i < cnt; i += 32) {
            u64 ki = lst[i];
            int rnk = 0;
            for (int j = 0; j < cnt; j++) rnk += (lst[j] < ki);
            if (rnk < NNB)
                g_cols[c * NNB + rnk] = (int)(unsigned)(ki & 0xffffffffu);
        }
        if (lane == 0) g_cnt[c] = NNB;
    }
}

// ---------------- exclusive scan of g_cnt (ENV CANARY — DO NOT TOUCH) ------
__global__ void __launch_bounds__(512, 1) scan_kernel() {
    __shared__ int s_ws[16];
    int tid = threadIdx.x, lane = tid & 31, warp = tid >> 5;
    int v[8], run = 0;
#pragma unroll
    for (int i = 0; i < 8; i++) { v[i] = g_cnt[tid * 8 + i]; run += v[i]; }
    int tot = run;
    int pre = tot;
#pragma unroll
    for (int o = 1; o < 32; o <<= 1) {
        int t = __shfl_up_sync(0xffffffffu, pre, o);
        if (lane >= o) pre += t;
    }
    if (lane == 31) s_ws[warp] = pre;
    int excl = pre - tot;
    __syncthreads();
    if (warp == 0) {
        int w = (lane < 16) ? s_ws[lane] : 0;
#pragma unroll
        for (int o = 1; o < 16; o <<= 1) {
            int t = __shfl_up_sync(0xffffffffu, w, o);
            if (lane >= o) w += t;
        }
        if (lane < 16) s_ws[lane] = w;
    }
    __syncthreads();
    int base = (warp > 0) ? s_ws[warp - 1] : 0;
    int off = base + excl;
#pragma unroll
    for (int i = 0; i < 8; i++) { g_off[tid * 8 + i] = off; off += v[i]; }
    if (tid == 511) g_nv = off;
}

// ---------------- row map: compacted row -> (center,slot) ------------------
__global__ void __launch_bounds__(256) rowmap_kernel() {
    int idx = blockIdx.x * 256 + threadIdx.x;
    int c = idx >> 5, s = idx & 31;
    if (s < g_cnt[c]) g_rows[g_off[c] + s] = idx;
}

// ---------------- gather + bias-pad (compacted rows only) ------------------
__global__ void __launch_bounds__(256) gather_kernel(const float* __restrict__ x) {
    int lane = threadIdx.x & 31;
    int warp = threadIdx.x >> 5;
    int nv = g_nv;
    float4 one0 = make_float4(1.f, 0.f, 0.f, 0.f);
    float4 z    = make_float4(0.f, 0.f, 0.f, 0.f);
    for (int r = blockIdx.x * 8 + warp; r < nv; r += 512 * 8) {
        int rid = g_rows[r];
        int c   = rid >> 5;
        int col = g_cols[rid];
        float* a = g_A + (size_t)r * KP;
        const float* xr = x + (size_t)col * 131 + 3 + 4 * lane;
        ((float4*)a)[lane] = make_float4(xr[0], xr[1], xr[2], xr[3]);
        if (lane < 4) {                      // A pad cols 128..143
            float4 e = z;
            if (lane == 0) {
                float4 p = g_pos4[col]; float4 ct = g_center[c];
                e = make_float4(p.x - ct.x, p.y - ct.y, p.z - ct.z, 1.0f);
            }
            ((float4*)a)[32 + lane] = e;
        } else if (lane < 8) {               // H1 bias cols
            ((float4*)(g_H1 + (size_t)r * KP + 128))[lane - 4] =
                (lane == 4) ? one0 : z;
        } else if (lane < 12) {              // H2 bias cols
            ((float4*)(g_H2 + (size_t)r * KP + 128))[lane - 8] =
                (lane == 8) ? one0 : z;
        }
    }
}

// ---------------- tiled fp32 GEMM + relu (early-exit past NV) --------------
template<int L>
__global__ void __launch_bounds__(256) sgemm_kernel() {
    size_t bRow = (size_t)blockIdx.x * 128;
    if ((int)bRow >= g_nv) return;
    const float* A = (L == 0) ? g_A  : (L == 1) ? g_H1 : g_H2;
    const float* B = (L == 0) ? g_W1p : (L == 1) ? g_W2p : g_W3p;
    float*       C = (L == 0) ? g_H1 : (L == 1) ? g_H2 : g_H3;
    const int ldb = (L == 2) ? 256 : 128;
    const int ldc = (L == 2) ? 256 : KP;

    __shared__ __align__(16) float As[16][132];
    __shared__ __align__(16) float Bs[16][132];
    int t  = threadIdx.x;
    int tx = t & 15, ty = t >> 4;
    int    bCol = blockIdx.y * 128;

    u64 acc[8][4];
#pragma unroll
    for (int i = 0; i < 8; i++)
#pragma unroll
        for (int p = 0; p < 4; p++) acc[i][p] = 0ull;

    for (int k0 = 0; k0 < KP; k0 += 16) {
#pragma unroll
        for (int e2 = 0; e2 < 2; e2++) {
            int e = t * 2 + e2;
            int r = e >> 2, c4 = e & 3;
            float4 f = *(const float4*)(A + (bRow + r) * KP + k0 + c4 * 4);
            As[c4 * 4 + 0][r] = f.x; As[c4 * 4 + 1][r] = f.y;
            As[c4 * 4 + 2][r] = f.z; As[c4 * 4 + 3][r] = f.w;
        }
#pragma unroll
        for (int e2 = 0; e2 < 2; e2++) {
            int e = t * 2 + e2;
            int r = e >> 5, c4 = e & 31;
            *(float4*)&Bs[r][c4 * 4] =
                *(const float4*)(B + (size_t)(k0 + r) * ldb + bCol + c4 * 4);
        }
        __syncthreads();
#pragma unroll
        for (int kk = 0; kk < 16; kk++) {
            longlong2 bb0 = *(const longlong2*)&Bs[kk][tx * 8];
            longlong2 bb1 = *(const longlong2*)&Bs[kk][tx * 8 + 4];
            u64 b[4] = { (u64)bb0.x, (u64)bb0.y, (u64)bb1.x, (u64)bb1.y };
            float4 a03 = *(const float4*)&As[kk][ty * 8];
            float4 a47 = *(const float4*)&As[kk][ty * 8 + 4];
            float a[8] = { a03.x, a03.y, a03.z, a03.w, a47.x, a47.y, a47.z, a47.w };
#pragma unroll
            for (int i = 0; i < 8; i++) {
                u64 aa = pk(a[i], a[i]);
#pragma unroll
                for (int p = 0; p < 4; p++) acc[i][p] = fma2(aa, b[p], acc[i][p]);
            }
        }
        __syncthreads();
    }
#pragma unroll
    for (int i = 0; i < 8; i++) {
        float* cr = C + (bRow + ty * 8 + i) * (size_t)ldc + bCol + tx * 8;
#pragma unroll
        for (int p = 0; p < 4; p++) {
            float lo, hi; upk(lo, hi, acc[i][p]);
            ((float2*)cr)[p] = make_float2(fmaxf(lo, 0.f), fmaxf(hi, 0.f));
        }
    }
}

// ---------------- masked max-pool over compacted rows ----------------------
__global__ void __launch_bounds__(256) pool_kernel(float* __restrict__ out) {
    int c = blockIdx.x, j = threadIdx.x;
    int off = g_off[c], cnt = g_cnt[c];
    float acc = 0.0f;
    if (cnt > 0) {
        acc = g_H3[(size_t)off * 256 + j];
        for (int s = 1; s < cnt; s++)
            acc = fmaxf(acc, g_H3[(size_t)(off + s) * 256 + j]);
    }
    out[(size_t)c * 256 + j] = acc;
}

// ---------------- launcher ----------------------------------------------
extern "C" void kernel_launch(void* const* d_in, const int* in_sizes, int n_in,
                              void* d_out, int out_size) {
    const float* x  = (const float*)d_in[0];
    const float* W1 = (const float*)d_in[1];
    const float* b1 = (const float*)d_in[2];
    const float* W2 = (const float*)d_in[3];
    const float* b2 = (const float*)d_in[4];
    const float* W3 = (const float*)d_in[5];
    const float* b3 = (const float*)d_in[6];
    float* out = (float*)d_out;

    cudaFuncSetAttribute(fps_kernel, cudaFuncAttributeMaxDynamicSharedMemorySize,
                         FPS_SMEM_BYTES);
    cudaFuncSetAttribute(knn_kernel, cudaFuncAttributeMaxDynamicSharedMemorySize,
                         KNN_SMEM_BYTES);

    prep_kernel<<<144, 256>>>(x, W1, b1, W2, b2, W3, b3);
    fps_kernel<<<CLSZ, 256, FPS_SMEM_BYTES>>>();
    knn_kernel<<<M_CTR / KNC, 512, KNN_SMEM_BYTES>>>();
    scan_kernel<<<1, 512>>>();
    rowmap_kernel<<<NROWS / 256, 256>>>();
    gather_kernel<<<512, 256>>>(x);
    sgemm_kernel<0><<<dim3(NROWS / 128, 1), 256>>>();
    sgemm_kernel<1><<<dim3(NROWS / 128, 1), 256>>>();
    sgemm_kernel<2><<<dim3(NROWS / 128, 2), 256>>>();
    pool_kernel<<<M_CTR, 256>>>(out);
}

// round 16
// speedup vs baseline: 1.3242x; 1.1059x over previous
#include <cuda_runtime.h>
#include <cuda_bf16.h>
#include <cstdint>

typedef unsigned long long u64;

#define N_PTS 16384
#define M_CTR 4096
#define NNB   32
#define R2F   0.04f
#define NROWS (M_CTR*NNB)
#define KP    144
#define CAP   256
#define CLSZ  8               // FPS cluster size
#define PPC   (N_PTS/CLSZ)    // 2048 points per CTA
#define FPT   8               // points per thread (256 thr/CTA)
#define NSLOT 16              // 8 CTAs x CTA-top2
#define KNC   16              // centers per knn CTA

// ---------------- device scratch ----------------------------------------
__device__ __align__(16) float4 g_pos4[N_PTS];
__device__ __align__(16) float4 g_center[M_CTR];
__device__ int   g_cols[NROWS];
__device__ int   g_cnt[M_CTR];
__device__ int   g_off[M_CTR];
__device__ int   g_nv;
__device__ int   g_rows[NROWS];
__device__ __align__(16) float g_W1p[KP*128];
__device__ __align__(16) float g_W2p[KP*128];
__device__ __align__(16) float g_W3p[KP*256];
__device__ __align__(16) float g_A [(size_t)NROWS*KP];
__device__ __align__(16) float g_H1[(size_t)NROWS*KP];
__device__ __align__(16) float g_H2[(size_t)NROWS*KP];
__device__ __align__(16) float g_H3[(size_t)NROWS*256];

// ---------------- f32x2 helpers -----------------------------------------
__device__ __forceinline__ u64 pk(float lo, float hi) {
    u64 r; asm("mov.b64 %0,{%1,%2};" : "=l"(r) : "f"(lo), "f"(hi)); return r;
}
__device__ __forceinline__ void upk(float& lo, float& hi, u64 v) {
    asm("mov.b64 {%0,%1},%2;" : "=f"(lo), "=f"(hi) : "l"(v));
}
__device__ __forceinline__ u64 add2(u64 a, u64 b) {
    u64 r; asm("add.rn.f32x2 %0,%1,%2;" : "=l"(r) : "l"(a), "l"(b)); return r;
}
__device__ __forceinline__ u64 mul2(u64 a, u64 b) {
    u64 r; asm("mul.rn.f32x2 %0,%1,%2;" : "=l"(r) : "l"(a), "l"(b)); return r;
}
__device__ __forceinline__ u64 fma2(u64 a, u64 b, u64 c) {
    u64 r; asm("fma.rn.f32x2 %0,%1,%2,%3;" : "=l"(r) : "l"(a), "l"(b), "l"(c)); return r;
}

// ---------------- cluster / mbarrier PTX helpers -------------------------
__device__ __forceinline__ unsigned sh_u32(const void* p) {
    return (unsigned)__cvta_generic_to_shared(p);
}
__device__ __forceinline__ unsigned mapa_sh(unsigned addr, unsigned rank) {
    unsigned r;
    asm("mapa.shared::cluster.u32 %0, %1, %2;" : "=r"(r) : "r"(addr), "r"(rank));
    return r;
}
__device__ __forceinline__ void mbar_init(unsigned a, unsigned cnt) {
    asm volatile("mbarrier.init.shared.b64 [%0], %1;" :: "r"(a), "r"(cnt) : "memory");
}
__device__ __forceinline__ void mbar_expect_tx(unsigned a, unsigned bytes) {
    asm volatile("mbarrier.arrive.expect_tx.shared::cta.b64 _, [%0], %1;"
                 :: "r"(a), "r"(bytes) : "memory");
}
__device__ __forceinline__ void st_async_u64(unsigned a, u64 v, unsigned mbar) {
    asm volatile("st.async.shared::cluster.mbarrier::complete_tx::bytes.b64 [%0], %1, [%2];"
                 :: "r"(a), "l"(v), "r"(mbar) : "memory");
}
__device__ __forceinline__ u64 ld_vol_sh_u64(unsigned a) {
    u64 r; asm volatile("ld.volatile.shared.u64 %0, [%1];" : "=l"(r) : "r"(a));
    return r;
}
__device__ __forceinline__ void cluster_sync_all() {
    asm volatile("barrier.cluster.arrive.aligned;" ::: "memory");
    asm volatile("barrier.cluster.wait.aligned;" ::: "memory");
}
__device__ __forceinline__ unsigned redux_max_u32(unsigned v) {
    unsigned r;
    asm("redux.sync.max.u32 %0, %1, 0xffffffff;" : "=r"(r) : "r"(v));
    return r;
}
// warp-wide exact u64 key max via two redux rounds (keys unique)
__device__ __forceinline__ u64 warp_max_key(u64 key) {
    unsigned vb = (unsigned)(key >> 32);
    unsigned mx = redux_max_u32(vb);
    unsigned cand = (vb == mx) ? (unsigned)key : 0u;
    unsigned lw = redux_max_u32(cand);
    return ((u64)mx << 32) | lw;
}

// ---------------- prep ----------------------------------------------------
__global__ void __launch_bounds__(256) prep_kernel(
    const float* __restrict__ x,
    const float* __restrict__ W1, const float* __restrict__ b1,
    const float* __restrict__ W2, const float* __restrict__ b2,
    const float* __restrict__ W3, const float* __restrict__ b3)
{
    int i = blockIdx.x * 256 + threadIdx.x;
    if (i < N_PTS) {
        const float* row = x + (size_t)i * 131;
        g_pos4[i] = make_float4(row[0], row[1], row[2], 0.f);
    }
    if (i < KP * 128) {
        int k = i >> 7, j = i & 127;
        g_W1p[i] = (k < 131) ? W1[k * 128 + j] : (k == 131 ? b1[j] : 0.f);
        g_W2p[i] = (k < 128) ? W2[k * 128 + j] : (k == 128 ? b2[j] : 0.f);
    }
    if (i < KP * 256) {
        int k = i >> 8, j = i & 255;
        g_W3p[i] = (k < 128) ? W3[k * 256 + j] : (k == 128 ? b3[j] : 0.f);
    }
}

// ---------------- FPS: CTA-top2 exchange + exact pairing -------------------
// Warps compute top-2 locally; warp0 reduces 16 keys -> CTA top-2 (exact by
// coverage), sends 2 keys to each of 8 CTAs (16 msgs, 16 slots). Global
// top-2 from CTA top-2s is exact. Pair condition d(r,w) >= min_d(r) proves
// r is the next winner -> consume two centers per exchange when it holds.
// Bit-identical to the sequential reference.
#define FPS_SMEM_BYTES (3 * N_PTS * 4)    // s_px/s_py/s_pz = 192KB

__global__ void __launch_bounds__(256, 1) __cluster_dims__(CLSZ, 1, 1)
fps_kernel() {
    extern __shared__ float s_dyn[];
    float* s_px = s_dyn;
    float* s_py = s_dyn + N_PTS;
    float* s_pz = s_dyn + 2 * N_PTS;
    __shared__ __align__(16) u64 s_mbk[2][NSLOT];   // [0..7] top1, [8..15] top2
    __shared__ __align__(16) u64 s_loc[2][16];      // per-warp top-2 staging
    __shared__ __align__(8)  u64 s_bar[2];

    int tid = threadIdx.x, lane = tid & 31, warp = tid >> 5;
    unsigned rank;
    asm("mov.u32 %0, %%cluster_ctarank;" : "=r"(rank));
    int pbase = (int)rank * PPC + tid;

    // full position replica in smem (one-time)
    for (int i = tid; i < N_PTS; i += 256) {
        float4 p = g_pos4[i];
        s_px[i] = p.x; s_py[i] = p.y; s_pz[i] = p.z;
    }
    // zero mailbox (tag field 0; exchange tags start at 1)
    if (tid < NSLOT) { s_mbk[0][tid] = 0ull; s_mbk[1][tid] = 0ull; }

    // own-shard coords register-resident; min_d as u32 bits
    u64 PX[4], PY[4], PZ[4];
    unsigned mb[FPT];
    unsigned nlo[FPT];                              // ~oidx, loop-invariant
#pragma unroll
    for (int q = 0; q < 4; q++) {
        float4 a = g_pos4[pbase + (2 * q) * 256];
        float4 b = g_pos4[pbase + (2 * q + 1) * 256];
        PX[q] = pk(a.x, b.x); PY[q] = pk(a.y, b.y); PZ[q] = pk(a.z, b.z);
        mb[2 * q] = 0x7f800000u;
        mb[2 * q + 1] = 0x7f800000u;
    }
#pragma unroll
    for (int i = 0; i < FPT; i++) nlo[i] = ~(unsigned)(pbase + i * 256);

    if (tid == 0) {
        mbar_init(sh_u32(&s_bar[0]), 1);   // tx bookkeeping only (never waited)
        mbar_init(sh_u32(&s_bar[1]), 1);
    }
    // send addresses (used by warp 0, lanes 0..15)
    unsigned dst = (unsigned)(lane & 7);
    int slotbase = (lane < 8) ? (int)rank : (8 + (int)rank);
    unsigned rab0 = mapa_sh(sh_u32(&s_bar[0]), dst);
    unsigned rab1 = mapa_sh(sh_u32(&s_bar[1]), dst);
    unsigned rak0 = mapa_sh(sh_u32(&s_mbk[0][slotbase]), dst);
    unsigned rak1 = mapa_sh(sh_u32(&s_mbk[1][slotbase]), dst);
    // poll addresses (lanes 0..15 poll slot lane)
    unsigned pp[2];
    pp[0] = sh_u32(&s_mbk[0][lane & 15]);
    pp[1] = sh_u32(&s_mbk[1][lane & 15]);

    __syncthreads();
    cluster_sync_all();     // mailbox zeros + replica visible before any send

    float4 c0 = g_pos4[0];
    float cx = c0.x, cy = c0.y, cz = c0.z;       // pending center 1
    float prx = 0.f, pry = 0.f, prz = 0.f;       // pending center 2 (if pair)
    int pair = 0;
    if (rank == 0 && tid == 0) g_center[0] = make_float4(cx, cy, cz, 0.f);

    int k = 1;
    unsigned e = 1;                               // exchange counter (tags)
    while (k < M_CTR) {
        int buf = (int)(e & 1u);
        unsigned tagk = e & 0xFFu;
        if (tid == 0) mbar_expect_tx(sh_u32(&s_bar[buf]), NSLOT * 8);

        // --- min_d update with pending center(s); exact reference order ---
        {
            u64 ncx = pk(-cx, -cx), ncy = pk(-cy, -cy), ncz = pk(-cz, -cz);
#pragma unroll
            for (int q = 0; q < 4; q++) {
                u64 dx = add2(PX[q], ncx);
                u64 dy = add2(PY[q], ncy);
                u64 dz = add2(PZ[q], ncz);
                u64 s  = add2(add2(mul2(dx, dx), mul2(dy, dy)), mul2(dz, dz));
                float d0, d1; upk(d0, d1, s);
                mb[2 * q]     = min(mb[2 * q],     __float_as_uint(d0));
                mb[2 * q + 1] = min(mb[2 * q + 1], __float_as_uint(d1));
            }
        }
        if (pair) {
            u64 ncx = pk(-prx, -prx), ncy = pk(-pry, -pry), ncz = pk(-prz, -prz);
#pragma unroll
            for (int q = 0; q < 4; q++) {
                u64 dx = add2(PX[q], ncx);
                u64 dy = add2(PY[q], ncy);
                u64 dz = add2(PZ[q], ncz);
                u64 s  = add2(add2(mul2(dx, dx), mul2(dy, dy)), mul2(dz, dz));
                float d0, d1; upk(d0, d1, s);
                mb[2 * q]     = min(mb[2 * q],     __float_as_uint(d0));
                mb[2 * q + 1] = min(mb[2 * q + 1], __float_as_uint(d1));
            }
        }

        // --- per-thread top-2 keys (tie -> min oidx via ~oidx low bits) ----
        u64 t1 = ((u64)mb[0] << 32) | nlo[0], t2 = 0ull;
#pragma unroll
        for (int i = 1; i < FPT; i++) {
            u64 ki = ((u64)mb[i] << 32) | nlo[i];
            if (ki > t1) { t2 = t1; t1 = ki; }
            else if (ki > t2) t2 = ki;
        }
        // --- warp top-2 via redux -----------------------------------------
        u64 w1 = warp_max_key(t1);
        u64 c2 = (t1 == w1) ? t2 : t1;
        u64 w2 = warp_max_key(c2);
        if (lane == 0) { s_loc[buf][warp] = w1; s_loc[buf][8 + warp] = w2; }
        __syncthreads();

        // --- warp 0: CTA top-2 from 16 staged keys, send to all CTAs -------
        if (warp == 0) {
            u64 kv = (lane < 16) ? s_loc[buf][lane] : 0ull;
            u64 ct1 = warp_max_key(kv);
            u64 cc = (kv == ct1) ? 0ull : kv;
            u64 ct2 = warp_max_key(cc);
            if (lane < 16) {
                u64 sel = (lane < 8) ? ct1 : ct2;
                unsigned lowm = (tagk << 24) | 0x00FFC000u | ((unsigned)sel & 0x3FFFu);
                u64 sv = (sel & 0xFFFFFFFF00000000ull) | (u64)lowm;
                st_async_u64(buf ? rak1 : rak0, sv, buf ? rab1 : rab0);
            }
        }

        // --- poll 16 slots for current tag --------------------------------
        u64 kv;
        {
            unsigned a = pp[buf];
            unsigned want = tagk << 24;
            while (true) {
                kv = (lane < 16) ? ld_vol_sh_u64(a) : 0ull;
                bool f = (lane >= 16) ||
                         ((((unsigned)kv ^ want) & 0xFF000000u) == 0u);
                if (__all_sync(0xffffffffu, f)) break;
            }
        }
        // --- global winner w and exact runner-up r -------------------------
        u64 wkey = warp_max_key(kv);
        u64 rc = (kv == wkey) ? 0ull : kv;
        u64 rkey = warp_max_key(rc);

        int widx = (int)((~(unsigned)wkey) & 0x3FFFu);
        int ridx = (int)((~(unsigned)rkey) & 0x3FFFu);
        float wx = s_px[widx], wy = s_py[widx], wz = s_pz[widx];

        // pair condition: d(r,w) >= min_d(r)  (same rn op order as updates)
        float rxc = s_px[ridx], ryc = s_py[ridx], rzc = s_pz[ridx];
        float ddx = __fadd_rn(rxc, -wx);
        float ddy = __fadd_rn(ryc, -wy);
        float ddz = __fadd_rn(rzc, -wz);
        float dd = __fadd_rn(__fadd_rn(__fmul_rn(ddx, ddx), __fmul_rn(ddy, ddy)),
                             __fmul_rn(ddz, ddz));
        bool cond = (__float_as_uint(dd) >= (unsigned)(rkey >> 32));

        // --- consume winner(s) ---------------------------------------------
        cx = wx; cy = wy; cz = wz;
        if (rank == 0 && tid == 0) g_center[k] = make_float4(cx, cy, cz, 0.f);
        if (cond && (k + 1 < M_CTR)) {
            prx = rxc; pry = ryc; prz = rzc;
            if (rank == 0 && tid == 0)
                g_center[k + 1] = make_float4(prx, pry, prz, 0.f);
            pair = 1; k += 2;
        } else {
            pair = 0; k += 1;
        }
        e++;
    }
    cluster_sync_all();
}

// ---------------- radius-KNN: 16 centers per CTA share tiles ---------------
#define KNN_SMEM_BYTES (65536 + KNC * CAP * 8)      // tiles 64KB + lists 32KB

__global__ void __launch_bounds__(512) knn_kernel() {
    extern __shared__ char sm_raw[];
    float4* s_t   = (float4*)sm_raw;                 // 4096 float4 = 64KB
    u64*    s_lst = (u64*)(sm_raw + 65536);          // KNC x CAP keys
    int tid = threadIdx.x, lane = tid & 31, warp = tid >> 5;
    int c = blockIdx.x * KNC + warp;
    u64* lst = s_lst + warp * CAP;
    float4 ct = g_center[c];

    int cnt = 0;
    for (int tile = 0; tile < 4; tile++) {
        __syncthreads();
        for (int i = tid; i < 4096; i += 512) s_t[i] = g_pos4[tile * 4096 + i];
        __syncthreads();
        for (int i = lane; i < 4096; i += 32) {
            float4 p = s_t[i];
            float dx = __fsub_rn(ct.x, p.x);
            float dy = __fsub_rn(ct.y, p.y);
            float dz = __fsub_rn(ct.z, p.z);
            float d2 = __fadd_rn(__fadd_rn(__fmul_rn(dx, dx), __fmul_rn(dy, dy)),
                                 __fmul_rn(dz, dz));
            bool ok = d2 <= R2F;
            unsigned mk = __ballot_sync(0xffffffffu, ok);
            if (ok) {
                int pos = cnt + __popc(mk & ((1u << lane) - 1u));
                if (pos < CAP)
                    lst[pos] = ((u64)__float_as_uint(d2) << 32)
                               | (unsigned)(tile * 4096 + i);
            }
            cnt += __popc(mk);
        }
    }
    if (cnt > CAP) cnt = CAP;
    __syncwarp();

    if (cnt <= NNB) {
        int v = (lane < cnt) ? (int)(unsigned)(lst[lane] & 0xffffffffu) : -1;
        g_cols[c * NNB + lane] = v;
        if (lane == 0) g_cnt[c] = cnt;
    } else {
        for (int i = lane; i < cnt; i += 32) {
            u64 ki = lst[i];
            int rnk = 0;
            for (int j = 0; j < cnt; j++) rnk += (lst[j] < ki);
            if (rnk < NNB)
                g_cols[c * NNB + rnk] = (int)(unsigned)(ki & 0xffffffffu);
        }
        if (lane == 0) g_cnt[c] = NNB;
    }
}

// ---------------- exclusive scan of g_cnt (ENV CANARY — DO NOT TOUCH) ------
__global__ void __launch_bounds__(512, 1) scan_kernel() {
    __shared__ int s_ws[16];
    int tid = threadIdx.x, lane = tid & 31, warp = tid >> 5;
    int v[8], run = 0;
#pragma unroll
    for (int i = 0; i < 8; i++) { v[i] = g_cnt[tid * 8 + i]; run += v[i]; }
    int tot = run;
    int pre = tot;
#pragma unroll
    for (int o = 1; o < 32; o <<= 1) {
        int t = __shfl_up_sync(0xffffffffu, pre, o);
        if (lane >= o) pre += t;
    }
    if (lane == 31) s_ws[warp] = pre;
    int excl = pre - tot;
    __syncthreads();
    if (warp == 0) {
        int w = (lane < 16) ? s_ws[lane] : 0;
#pragma unroll
        for (int o = 1; o < 16; o <<= 1) {
            int t = __shfl_up_sync(0xffffffffu, w, o);
            if (lane >= o) w += t;
        }
        if (lane < 16) s_ws[lane] = w;
    }
    __syncthreads();
    int base = (warp > 0) ? s_ws[warp - 1] : 0;
    int off = base + excl;
#pragma unroll
    for (int i = 0; i < 8; i++) { g_off[tid * 8 + i] = off; off += v[i]; }
    if (tid == 511) g_nv = off;
}

// ---------------- row map: compacted row -> (center,slot) ------------------
__global__ void __launch_bounds__(256) rowmap_kernel() {
    int idx = blockIdx.x * 256 + threadIdx.x;
    int c = idx >> 5, s = idx & 31;
    if (s < g_cnt[c]) g_rows[g_off[c] + s] = idx;
}

// ---------------- gather + bias-pad (compacted rows only) ------------------
__global__ void __launch_bounds__(256) gather_kernel(const float* __restrict__ x) {
    int lane = threadIdx.x & 31;
    int warp = threadIdx.x >> 5;
    int nv = g_nv;
    float4 one0 = make_float4(1.f, 0.f, 0.f, 0.f);
    float4 z    = make_float4(0.f, 0.f, 0.f, 0.f);
    for (int r = blockIdx.x * 8 + warp; r < nv; r += 512 * 8) {
        int rid = g_rows[r];
        int c   = rid >> 5;
        int col = g_cols[rid];
        float* a = g_A + (size_t)r * KP;
        const float* xr = x + (size_t)col * 131 + 3 + 4 * lane;
        ((float4*)a)[lane] = make_float4(xr[0], xr[1], xr[2], xr[3]);
        if (lane < 4) {                      // A pad cols 128..143
            float4 e = z;
            if (lane == 0) {
                float4 p = g_pos4[col]; float4 ct = g_center[c];
                e = make_float4(p.x - ct.x, p.y - ct.y, p.z - ct.z, 1.0f);
            }
            ((float4*)a)[32 + lane] = e;
        } else if (lane < 8) {               // H1 bias cols
            ((float4*)(g_H1 + (size_t)r * KP + 128))[lane - 4] =
                (lane == 4) ? one0 : z;
        } else if (lane < 12) {              // H2 bias cols
            ((float4*)(g_H2 + (size_t)r * KP + 128))[lane - 8] =
                (lane == 8) ? one0 : z;
        }
    }
}

// ---------------- tiled fp32 GEMM + relu (early-exit past NV) --------------
template<int L>
__global__ void __launch_bounds__(256) sgemm_kernel() {
    size_t bRow = (size_t)blockIdx.x * 128;
    if ((int)bRow >= g_nv) return;
    const float* A = (L == 0) ? g_A  : (L == 1) ? g_H1 : g_H2;
    const float* B = (L == 0) ? g_W1p : (L == 1) ? g_W2p : g_W3p;
    float*       C = (L == 0) ? g_H1 : (L == 1) ? g_H2 : g_H3;
    const int ldb = (L == 2) ? 256 : 128;
    const int ldc = (L == 2) ? 256 : KP;

    __shared__ __align__(16) float As[16][132];
    __shared__ __align__(16) float Bs[16][132];
    int t  = threadIdx.x;
    int tx = t & 15, ty = t >> 4;
    int    bCol = blockIdx.y * 128;

    u64 acc[8][4];
#pragma unroll
    for (int i = 0; i < 8; i++)
#pragma unroll
        for (int p = 0; p < 4; p++) acc[i][p] = 0ull;

    for (int k0 = 0; k0 < KP; k0 += 16) {
#pragma unroll
        for (int e2 = 0; e2 < 2; e2++) {
            int e = t * 2 + e2;
            int r = e >> 2, c4 = e & 3;
            float4 f = *(const float4*)(A + (bRow + r) * KP + k0 + c4 * 4);
            As[c4 * 4 + 0][r] = f.x; As[c4 * 4 + 1][r] = f.y;
            As[c4 * 4 + 2][r] = f.z; As[c4 * 4 + 3][r] = f.w;
        }
#pragma unroll
        for (int e2 = 0; e2 < 2; e2++) {
            int e = t * 2 + e2;
            int r = e >> 5, c4 = e & 31;
            *(float4*)&Bs[r][c4 * 4] =
                *(const float4*)(B + (size_t)(k0 + r) * ldb + bCol + c4 * 4);
        }
        __syncthreads();
#pragma unroll
        for (int kk = 0; kk < 16; kk++) {
            longlong2 bb0 = *(const longlong2*)&Bs[kk][tx * 8];
            longlong2 bb1 = *(const longlong2*)&Bs[kk][tx * 8 + 4];
            u64 b[4] = { (u64)bb0.x, (u64)bb0.y, (u64)bb1.x, (u64)bb1.y };
            float4 a03 = *(const float4*)&As[kk][ty * 8];
            float4 a47 = *(const float4*)&As[kk][ty * 8 + 4];
            float a[8] = { a03.x, a03.y, a03.z, a03.w, a47.x, a47.y, a47.z, a47.w };
#pragma unroll
            for (int i = 0; i < 8; i++) {
                u64 aa = pk(a[i], a[i]);
#pragma unroll
                for (int p = 0; p < 4; p++) acc[i][p] = fma2(aa, b[p], acc[i][p]);
            }
        }
        __syncthreads();
    }
#pragma unroll
    for (int i = 0; i < 8; i++) {
        float* cr = C + (bRow + ty * 8 + i) * (size_t)ldc + bCol + tx * 8;
#pragma unroll
        for (int p = 0; p < 4; p++) {
            float lo, hi; upk(lo, hi, acc[i][p]);
            ((float2*)cr)[p] = make_float2(fmaxf(lo, 0.f), fmaxf(hi, 0.f));
        }
    }
}

// ---------------- masked max-pool over compacted rows ----------------------
__global__ void __launch_bounds__(256) pool_kernel(float* __restrict__ out) {
    int c = blockIdx.x, j = threadIdx.x;
    int off = g_off[c], cnt = g_cnt[c];
    float acc = 0.0f;
    if (cnt > 0) {
        acc = g_H3[(size_t)off * 256 + j];
        for (int s = 1; s < cnt; s++)
            acc = fmaxf(acc, g_H3[(size_t)(off + s) * 256 + j]);
    }
    out[(size_t)c * 256 + j] = acc;
}

// ---------------- launcher ----------------------------------------------
extern "C" void kernel_launch(void* const* d_in, const int* in_sizes, int n_in,
                              void* d_out, int out_size) {
    const float* x  = (const float*)d_in[0];
    const float* W1 = (const float*)d_in[1];
    const float* b1 = (const float*)d_in[2];
    const float* W2 = (const float*)d_in[3];
    const float* b2 = (const float*)d_in[4];
    const float* W3 = (const float*)d_in[5];
    const float* b3 = (const float*)d_in[6];
    float* out = (float*)d_out;

    cudaFuncSetAttribute(fps_kernel, cudaFuncAttributeMaxDynamicSharedMemorySize,
                         FPS_SMEM_BYTES);
    cudaFuncSetAttribute(knn_kernel, cudaFuncAttributeMaxDynamicSharedMemorySize,
                         KNN_SMEM_BYTES);

    prep_kernel<<<144, 256>>>(x, W1, b1, W2, b2, W3, b3);
    fps_kernel<<<CLSZ, 256, FPS_SMEM_BYTES>>>();
    knn_kernel<<<M_CTR / KNC, 512, KNN_SMEM_BYTES>>>();
    scan_kernel<<<1, 512>>>();
    rowmap_kernel<<<NROWS / 256, 256>>>();
    gather_kernel<<<512, 256>>>(x);
    sgemm_kernel<0><<<dim3(NROWS / 128, 1), 256>>>();
    sgemm_kernel<1><<<dim3(NROWS / 128, 1), 256>>>();
    sgemm_kernel<2><<<dim3(NROWS / 128, 2), 256>>>();
    pool_kernel<<<M_CTR, 256>>>(out);
}